// round 1
// baseline (speedup 1.0000x reference)
#include <cuda_runtime.h>
#include <math.h>

#define CN 131072
#define CE 524288
#define CG 4096
#define DIN 128
#define DH  512
#define DOUTD 256
#define BN_EPS 1e-5f

// ---------------- scratch (static device globals; no allocation) -------------
__device__ float g_deg[CN];
__device__ float g_dinv[CN];
__device__ float g_norm[CE];
__device__ float g_agg1[(size_t)CN * DIN];    // 64 MB
__device__ float g_h1  [(size_t)CN * DH];     // 256 MB
__device__ float g_t2  [(size_t)CN * DH];     // 256 MB
__device__ float g_a2  [(size_t)CN * DH];     // 256 MB
__device__ float g_t3  [(size_t)CN * DOUTD]; // 128 MB
__device__ float g_a3  [(size_t)CN * DOUTD]; // 128 MB
__device__ float g_sums[(size_t)CG * DOUTD];
__device__ float g_cnt [CG];
__device__ float g_pool[(size_t)CG * DOUTD];
__device__ float g_mlp1[(size_t)CG * DOUTD];

// ---------------- degree / norm ---------------------------------------------
__global__ void k_deg_init(float* __restrict__ deg) {
    unsigned i = blockIdx.x * blockDim.x + threadIdx.x;
    if (i < CN) deg[i] = 1.0f;  // self-loop
}

__global__ void k_deg_edges(const int* __restrict__ dst, float* __restrict__ deg) {
    unsigned e = blockIdx.x * blockDim.x + threadIdx.x;
    if (e < CE) atomicAdd(&deg[dst[e]], 1.0f);
}

__global__ void k_dinv(const float* __restrict__ deg, float* __restrict__ dinv) {
    unsigned i = blockIdx.x * blockDim.x + threadIdx.x;
    if (i < CN) dinv[i] = rsqrtf(deg[i]);
}

__global__ void k_norm(const int* __restrict__ src, const int* __restrict__ dst,
                       const float* __restrict__ dinv, float* __restrict__ norm) {
    unsigned e = blockIdx.x * blockDim.x + threadIdx.x;
    if (e < CE) norm[e] = dinv[src[e]] * dinv[dst[e]];
}

// ---------------- aggregation ------------------------------------------------
// self-loop term: out[n] = in[n] * dinv[n]^2   (also serves as buffer init)
template <int D>
__global__ void k_agg_self(const float* __restrict__ in, const float* __restrict__ dinv,
                           float* __restrict__ out) {
    unsigned idx = blockIdx.x * blockDim.x + threadIdx.x;
    if (idx >= (unsigned)CN * D) return;
    unsigned n = idx / D;  // D is a power of two -> shift
    float di = dinv[n];
    out[idx] = in[idx] * di * di;
}

// one warp per edge; float4 gather from src row, scalar atomics to dst row
template <int D>
__global__ void k_agg_edges(const float* __restrict__ in, float* __restrict__ out,
                            const int* __restrict__ src, const int* __restrict__ dst,
                            const float* __restrict__ norm) {
    unsigned gtid = blockIdx.x * blockDim.x + threadIdx.x;
    unsigned e = gtid >> 5;
    unsigned lane = gtid & 31;
    if (e >= CE) return;
    int s = src[e], d = dst[e];
    float w = norm[e];
    const float4* ip = reinterpret_cast<const float4*>(in + (size_t)s * D);
    float* op = out + (size_t)d * D;
#pragma unroll
    for (int i = 0; i < D / 128; i++) {
        float4 v = ip[lane + i * 32];
        int c = (lane + i * 32) * 4;
        atomicAdd(op + c + 0, v.x * w);
        atomicAdd(op + c + 1, v.y * w);
        atomicAdd(op + c + 2, v.z * w);
        atomicAdd(op + c + 3, v.w * w);
    }
}

// post-aggregation bias + relu + eval-BN, in-place
template <int D>
__global__ void k_bnrelu(float* __restrict__ a, const float* __restrict__ bias,
                         const float* __restrict__ ga, const float* __restrict__ be,
                         const float* __restrict__ mu, const float* __restrict__ va) {
    unsigned idx = blockIdx.x * blockDim.x + threadIdx.x;
    if (idx >= (unsigned)CN * D) return;
    unsigned c = idx & (D - 1);
    float v = a[idx] + bias[c];
    v = fmaxf(v, 0.0f);
    float s = ga[c] * rsqrtf(va[c] + BN_EPS);
    a[idx] = v * s + (be[c] - mu[c] * s);
}

// ---------------- SGEMM: C[M,Nn] = A[M,K] @ W[K,Nn] + epilogue ---------------
// EPI: 0=none, 1=bias+relu+BN, 2=bias+relu, 3=bias
// Requires M%128==0, Nn%128==0, K%16==0 (true for every call here).
template <int EPI>
__global__ __launch_bounds__(256) void k_sgemm(
    const float* __restrict__ A, const float* __restrict__ W, float* __restrict__ C,
    int M, int K, int Nn,
    const float* __restrict__ bias, const float* __restrict__ ga,
    const float* __restrict__ be, const float* __restrict__ mu,
    const float* __restrict__ va) {
    __shared__ float As[16][128];
    __shared__ float Bs[16][128];
    const int tid = threadIdx.x;
    const int bc = blockIdx.x, br = blockIdx.y;

    const int aRow = tid >> 2;          // 0..63 (two rows: aRow, aRow+64)
    const int aCol = (tid & 3) * 4;     // 0,4,8,12
    const int bRow = tid >> 5;          // 0..7 (two rows: bRow, bRow+8)
    const int bCol = (tid & 31) * 4;    // 0..124
    const int tr = (tid >> 4) * 8;
    const int tc = (tid & 15) * 8;

    const float* Ablk = A + (size_t)br * 128 * K;
    const float* Wblk = W + bc * 128;

    float acc[8][8];
#pragma unroll
    for (int i = 0; i < 8; i++)
#pragma unroll
        for (int j = 0; j < 8; j++) acc[i][j] = 0.0f;

    for (int k0 = 0; k0 < K; k0 += 16) {
        float4 a0 = *reinterpret_cast<const float4*>(Ablk + (size_t)aRow * K + k0 + aCol);
        float4 a1 = *reinterpret_cast<const float4*>(Ablk + (size_t)(aRow + 64) * K + k0 + aCol);
        As[aCol + 0][aRow] = a0.x; As[aCol + 1][aRow] = a0.y;
        As[aCol + 2][aRow] = a0.z; As[aCol + 3][aRow] = a0.w;
        As[aCol + 0][aRow + 64] = a1.x; As[aCol + 1][aRow + 64] = a1.y;
        As[aCol + 2][aRow + 64] = a1.z; As[aCol + 3][aRow + 64] = a1.w;
        *reinterpret_cast<float4*>(&Bs[bRow][bCol]) =
            *reinterpret_cast<const float4*>(Wblk + (size_t)(k0 + bRow) * Nn + bCol);
        *reinterpret_cast<float4*>(&Bs[bRow + 8][bCol]) =
            *reinterpret_cast<const float4*>(Wblk + (size_t)(k0 + bRow + 8) * Nn + bCol);
        __syncthreads();
#pragma unroll
        for (int kk = 0; kk < 16; kk++) {
            float ar[8], bb[8];
#pragma unroll
            for (int i = 0; i < 8; i++) ar[i] = As[kk][tr + i];
#pragma unroll
            for (int j = 0; j < 8; j++) bb[j] = Bs[kk][tc + j];
#pragma unroll
            for (int i = 0; i < 8; i++)
#pragma unroll
                for (int j = 0; j < 8; j++) acc[i][j] += ar[i] * bb[j];
        }
        __syncthreads();
    }

    // per-column epilogue constants (same for all 8 rows of this thread)
    float cb[8], cs[8], csh[8];
#pragma unroll
    for (int j = 0; j < 8; j++) {
        int col = bc * 128 + tc + j;
        cb[j] = (EPI != 0) ? bias[col] : 0.0f;
        if (EPI == 1) {
            float s = ga[col] * rsqrtf(va[col] + BN_EPS);
            cs[j] = s;
            csh[j] = be[col] - mu[col] * s;
        } else {
            cs[j] = 1.0f;
            csh[j] = 0.0f;
        }
    }

#pragma unroll
    for (int i = 0; i < 8; i++) {
        int row = br * 128 + tr + i;
        float* Crow = C + (size_t)row * Nn + bc * 128 + tc;
        float vals[8];
#pragma unroll
        for (int j = 0; j < 8; j++) {
            float v = acc[i][j];
            if (EPI != 0) v += cb[j];
            if (EPI == 1 || EPI == 2) v = fmaxf(v, 0.0f);
            if (EPI == 1) v = v * cs[j] + csh[j];
            vals[j] = v;
        }
        *reinterpret_cast<float4*>(Crow + 0) = make_float4(vals[0], vals[1], vals[2], vals[3]);
        *reinterpret_cast<float4*>(Crow + 4) = make_float4(vals[4], vals[5], vals[6], vals[7]);
    }
}

// ---------------- pooling ----------------------------------------------------
__global__ void k_pool_zero(float* __restrict__ sums, float* __restrict__ cnt) {
    unsigned idx = blockIdx.x * blockDim.x + threadIdx.x;
    if (idx < (unsigned)CG * DOUTD) sums[idx] = 0.0f;
    if (idx < CG) cnt[idx] = 0.0f;
}

__global__ void k_pool_cnt(const int* __restrict__ batch, float* __restrict__ cnt) {
    unsigned n = blockIdx.x * blockDim.x + threadIdx.x;
    if (n < CN) atomicAdd(&cnt[batch[n]], 1.0f);
}

__global__ void k_pool_sum(const float* __restrict__ h, const int* __restrict__ batch,
                           float* __restrict__ sums) {
    unsigned idx = blockIdx.x * blockDim.x + threadIdx.x;
    if (idx >= (unsigned)CN * DOUTD) return;
    unsigned n = idx >> 8;        // /256
    unsigned c = idx & 255;
    atomicAdd(&sums[((unsigned)batch[n] << 8) + c], h[idx]);
}

__global__ void k_pooled(const float* __restrict__ sums, const float* __restrict__ cnt,
                         float* __restrict__ pooled) {
    unsigned idx = blockIdx.x * blockDim.x + threadIdx.x;
    if (idx >= (unsigned)CG * DOUTD) return;
    unsigned g = idx >> 8;
    pooled[idx] = sums[idx] / fmaxf(cnt[g], 1.0f);
}

// ---------------- launch -----------------------------------------------------
extern "C" void kernel_launch(void* const* d_in, const int* in_sizes, int n_in,
                              void* d_out, int out_size) {
    const float* x   = (const float*)d_in[0];
    const int* ei    = (const int*)d_in[1];   // [2, E]: row0=src, row1=dst
    const int* batch = (const int*)d_in[2];
    const float* W1  = (const float*)d_in[3];  const float* b1  = (const float*)d_in[4];
    const float* W2  = (const float*)d_in[5];  const float* b2  = (const float*)d_in[6];
    const float* W3  = (const float*)d_in[7];  const float* b3  = (const float*)d_in[8];
    const float* g1  = (const float*)d_in[9];  const float* be1 = (const float*)d_in[10];
    const float* m1  = (const float*)d_in[11]; const float* v1  = (const float*)d_in[12];
    const float* g2  = (const float*)d_in[13]; const float* be2 = (const float*)d_in[14];
    const float* m2  = (const float*)d_in[15]; const float* v2  = (const float*)d_in[16];
    const float* g3  = (const float*)d_in[17]; const float* be3 = (const float*)d_in[18];
    const float* m3  = (const float*)d_in[19]; const float* v3  = (const float*)d_in[20];
    const float* Wf1 = (const float*)d_in[21]; const float* bf1 = (const float*)d_in[22];
    const float* Wf2 = (const float*)d_in[23]; const float* bf2 = (const float*)d_in[24];
    float* out = (float*)d_out;

    const int* src = ei;
    const int* dst = ei + CE;

    float *deg, *dinv, *norm, *agg1, *h1, *t2, *a2, *t3, *a3, *sums, *cnt, *pool, *mlp1;
    cudaGetSymbolAddress((void**)&deg,  g_deg);
    cudaGetSymbolAddress((void**)&dinv, g_dinv);
    cudaGetSymbolAddress((void**)&norm, g_norm);
    cudaGetSymbolAddress((void**)&agg1, g_agg1);
    cudaGetSymbolAddress((void**)&h1,   g_h1);
    cudaGetSymbolAddress((void**)&t2,   g_t2);
    cudaGetSymbolAddress((void**)&a2,   g_a2);
    cudaGetSymbolAddress((void**)&t3,   g_t3);
    cudaGetSymbolAddress((void**)&a3,   g_a3);
    cudaGetSymbolAddress((void**)&sums, g_sums);
    cudaGetSymbolAddress((void**)&cnt,  g_cnt);
    cudaGetSymbolAddress((void**)&pool, g_pool);
    cudaGetSymbolAddress((void**)&mlp1, g_mlp1);

    const int T = 256;
    // degree / normalization
    k_deg_init<<<(CN + T - 1) / T, T>>>(deg);
    k_deg_edges<<<(CE + T - 1) / T, T>>>(dst, deg);
    k_dinv<<<(CN + T - 1) / T, T>>>(deg, dinv);
    k_norm<<<(CE + T - 1) / T, T>>>(src, dst, dinv, norm);

    // ---- layer 1: aggregate FIRST at D=128 (A x) then GEMM ----
    k_agg_self<DIN><<<((unsigned)CN * DIN + T - 1) / T, T>>>(x, dinv, agg1);
    k_agg_edges<DIN><<<(CE * 32 + T - 1) / T, T>>>(x, agg1, src, dst, norm);
    {
        dim3 grid(DH / 128, CN / 128);
        k_sgemm<1><<<grid, 256>>>(agg1, W1, h1, CN, DIN, DH, b1, g1, be1, m1, v1);
    }

    // ---- layer 2: GEMM then aggregate at D=512 ----
    {
        dim3 grid(DH / 128, CN / 128);
        k_sgemm<0><<<grid, 256>>>(h1, W2, t2, CN, DH, DH, nullptr, nullptr, nullptr, nullptr, nullptr);
    }
    k_agg_self<DH><<<((unsigned)CN * DH + T - 1) / T, T>>>(t2, dinv, a2);
    k_agg_edges<DH><<<(CE * 32 + T - 1) / T, T>>>(t2, a2, src, dst, norm);
    k_bnrelu<DH><<<((unsigned)CN * DH + T - 1) / T, T>>>(a2, b2, g2, be2, m2, v2);

    // ---- layer 3: GEMM then aggregate at D=256 ----
    {
        dim3 grid(DOUTD / 128, CN / 128);
        k_sgemm<0><<<grid, 256>>>(a2, W3, t3, CN, DH, DOUTD, nullptr, nullptr, nullptr, nullptr, nullptr);
    }
    k_agg_self<DOUTD><<<((unsigned)CN * DOUTD + T - 1) / T, T>>>(t3, dinv, a3);
    k_agg_edges<DOUTD><<<(CE * 32 + T - 1) / T, T>>>(t3, a3, src, dst, norm);
    k_bnrelu<DOUTD><<<((unsigned)CN * DOUTD + T - 1) / T, T>>>(a3, b3, g3, be3, m3, v3);

    // ---- mean pool ----
    k_pool_zero<<<((unsigned)CG * DOUTD + T - 1) / T, T>>>(sums, cnt);
    k_pool_cnt<<<(CN + T - 1) / T, T>>>(batch, cnt);
    k_pool_sum<<<((unsigned)CN * DOUTD + T - 1) / T, T>>>(a3, batch, sums);
    k_pooled<<<((unsigned)CG * DOUTD + T - 1) / T, T>>>(sums, cnt, pool);

    // ---- MLP head ----
    {
        dim3 grid(DOUTD / 128, CG / 128);
        k_sgemm<2><<<grid, 256>>>(pool, Wf1, mlp1, CG, DOUTD, DOUTD, bf1, nullptr, nullptr, nullptr, nullptr);
        k_sgemm<3><<<grid, 256>>>(mlp1, Wf2, out, CG, DOUTD, DOUTD, bf2, nullptr, nullptr, nullptr, nullptr);
    }
}

// round 2
// speedup vs baseline: 1.4824x; 1.4824x over previous
#include <cuda_runtime.h>
#include <math.h>

#define CN 131072
#define CE 524288
#define CG 4096
#define DIN 128
#define DH  512
#define DOUTD 256
#define BN_EPS 1e-5f

// ---------------- scratch (static device globals; no allocation) -------------
__device__ float g_dinv[CN];
__device__ int   g_cnt [CN];
__device__ int   g_noff[CN + 1];
__device__ int   g_cur [CN];
__device__ int   g_bsum[512];
__device__ int   g_csrc[CE];
__device__ float g_cw  [CE];
__device__ int   g_gcnt[CG];
__device__ int   g_goff[CG + 1];
__device__ int   g_gbsum[16];
__device__ float g_bns [DH + DOUTD];   // BN scale for layers 2,3
__device__ float g_bnsh[DH + DOUTD];   // BN shift for layers 2,3
__device__ float g_agg1[(size_t)CN * DIN];
__device__ float g_h1  [(size_t)CN * DH];
__device__ float g_t2  [(size_t)CN * DH];
__device__ float g_a2  [(size_t)CN * DH];
__device__ float g_t3  [(size_t)CN * DOUTD];
__device__ float g_a3  [(size_t)CN * DOUTD];
__device__ float g_pool[(size_t)CG * DOUTD];
__device__ float g_mlp1[(size_t)CG * DOUTD];

// ---------------- small utility kernels --------------------------------------
__global__ void k_zero_i(int* __restrict__ p, int n) {
    unsigned i = blockIdx.x * blockDim.x + threadIdx.x;
    if (i < (unsigned)n) p[i] = 0;
}

__global__ void k_hist(const int* __restrict__ keys, int n, int* __restrict__ cnt) {
    unsigned i = blockIdx.x * blockDim.x + threadIdx.x;
    if (i < (unsigned)n) atomicAdd(&cnt[keys[i]], 1);
}

__global__ void k_dinv_from_cnt(const int* __restrict__ cnt, float* __restrict__ dinv) {
    unsigned i = blockIdx.x * blockDim.x + threadIdx.x;
    if (i < CN) dinv[i] = rsqrtf((float)(cnt[i] + 1));
}

// blockwise exclusive scan (256/block), 2-level
__global__ void k_scan_block(const int* __restrict__ in, int* __restrict__ out,
                             int* __restrict__ bsum, int n) {
    __shared__ int sh[256];
    int t = threadIdx.x;
    int i = blockIdx.x * 256 + t;
    int v = (i < n) ? in[i] : 0;
    sh[t] = v; __syncthreads();
#pragma unroll
    for (int o = 1; o < 256; o <<= 1) {
        int x = (t >= o) ? sh[t - o] : 0;
        __syncthreads();
        sh[t] += x;
        __syncthreads();
    }
    if (i < n) out[i] = sh[t] - v;          // exclusive
    if (t == 255) bsum[blockIdx.x] = sh[255];
}

__global__ void k_scan_partials(int* __restrict__ bsum, int nb) {
    __shared__ int sh[1024];
    int t = threadIdx.x;
    int v = (t < nb) ? bsum[t] : 0;
    sh[t] = v; __syncthreads();
#pragma unroll
    for (int o = 1; o < 1024; o <<= 1) {
        int x = (t >= o) ? sh[t - o] : 0;
        __syncthreads();
        sh[t] += x;
        __syncthreads();
    }
    if (t < nb) bsum[t] = sh[t] - v;        // exclusive
}

__global__ void k_scan_add(int* __restrict__ out, const int* __restrict__ bsum,
                           int n, int total) {
    unsigned i = blockIdx.x * blockDim.x + threadIdx.x;
    if (i < (unsigned)n) out[i] += bsum[i >> 8];
    if (i == 0) out[n] = total;
}

// scatter edges into CSR buckets; weight = dinv[src]*dinv[dst]
__global__ void k_csr_scatter(const int* __restrict__ src, const int* __restrict__ dst,
                              const float* __restrict__ dinv,
                              const int* __restrict__ noff, int* __restrict__ cur,
                              int* __restrict__ csrc, float* __restrict__ cw) {
    unsigned e = blockIdx.x * blockDim.x + threadIdx.x;
    if (e >= CE) return;
    int d = dst[e], s = src[e];
    int pos = noff[d] + atomicAdd(&cur[d], 1);
    csrc[pos] = s;
    cw[pos] = dinv[s] * dinv[d];
}

__global__ void k_bnprep(const float* __restrict__ g, const float* __restrict__ be,
                         const float* __restrict__ m, const float* __restrict__ v,
                         float* __restrict__ s, float* __restrict__ sh, int n) {
    unsigned i = blockIdx.x * blockDim.x + threadIdx.x;
    if (i >= (unsigned)n) return;
    float sc = g[i] * rsqrtf(v[i] + BN_EPS);
    s[i] = sc;
    sh[i] = be[i] - m[i] * sc;
}

// ---------------- CSR aggregation (gather, no atomics) ------------------------
// out[d] = (optionally bn(relu( t[d]*dinv[d]^2 + sum_e w*t[src] + bias )))
// D floats per node; TPN = D/4 threads per node; 128-thread blocks.
template <int D, bool BN>
__global__ __launch_bounds__(128) void k_agg_csr(
    const float* __restrict__ t, float* __restrict__ out,
    const int* __restrict__ noff, const int* __restrict__ csrc,
    const float* __restrict__ cw, const float* __restrict__ dinv,
    const float* __restrict__ bias, const float* __restrict__ bns,
    const float* __restrict__ bnsh) {
    constexpr int TPN = D / 4;
    constexpr int NPB = 128 / TPN;
    int node = blockIdx.x * NPB + threadIdx.x / TPN;
    int lane = threadIdx.x % TPN;
    int c = lane * 4;

    float di = dinv[node];
    float4 acc = *reinterpret_cast<const float4*>(t + (size_t)node * D + c);
    float w0 = di * di;
    acc.x *= w0; acc.y *= w0; acc.z *= w0; acc.w *= w0;

    int beg = noff[node], end = noff[node + 1];
    for (int p = beg; p < end; p++) {
        int s = csrc[p];
        float w = cw[p];
        float4 v = *reinterpret_cast<const float4*>(t + (size_t)s * D + c);
        acc.x += v.x * w; acc.y += v.y * w; acc.z += v.z * w; acc.w += v.w * w;
    }
    if (BN) {
        float4 b = *reinterpret_cast<const float4*>(bias + c);
        float4 s4 = *reinterpret_cast<const float4*>(bns + c);
        float4 h4 = *reinterpret_cast<const float4*>(bnsh + c);
        acc.x = fmaxf(acc.x + b.x, 0.0f) * s4.x + h4.x;
        acc.y = fmaxf(acc.y + b.y, 0.0f) * s4.y + h4.y;
        acc.z = fmaxf(acc.z + b.z, 0.0f) * s4.z + h4.z;
        acc.w = fmaxf(acc.w + b.w, 0.0f) * s4.w + h4.w;
    }
    *reinterpret_cast<float4*>(out + (size_t)node * D + c) = acc;
}

// ---------------- segment mean pool (batch is sorted) -------------------------
__global__ __launch_bounds__(128) void k_pool_seg(const float* __restrict__ h,
                                                  const int* __restrict__ goff,
                                                  float* __restrict__ pooled) {
    int g = blockIdx.x * 2 + threadIdx.x / 64;
    int lane = threadIdx.x % 64;
    int c = lane * 4;
    int beg = goff[g], end = goff[g + 1];
    float4 acc = make_float4(0.f, 0.f, 0.f, 0.f);
    for (int n = beg; n < end; n++) {
        float4 v = *reinterpret_cast<const float4*>(h + (size_t)n * DOUTD + c);
        acc.x += v.x; acc.y += v.y; acc.z += v.z; acc.w += v.w;
    }
    float inv = 1.0f / fmaxf((float)(end - beg), 1.0f);
    acc.x *= inv; acc.y *= inv; acc.z *= inv; acc.w *= inv;
    *reinterpret_cast<float4*>(pooled + (size_t)g * DOUTD + c) = acc;
}

// ---------------- SGEMM: C[M,Nn] = A[M,K] @ W[K,Nn] + epilogue ---------------
// EPI: 0=none, 1=bias+relu+BN, 2=bias+relu, 3=bias
template <int EPI>
__global__ __launch_bounds__(256) void k_sgemm(
    const float* __restrict__ A, const float* __restrict__ W, float* __restrict__ C,
    int M, int K, int Nn,
    const float* __restrict__ bias, const float* __restrict__ ga,
    const float* __restrict__ be, const float* __restrict__ mu,
    const float* __restrict__ va) {
    __shared__ float As[16][128];
    __shared__ float Bs[16][128];
    const int tid = threadIdx.x;
    const int bc = blockIdx.x, br = blockIdx.y;

    const int aRow = tid >> 2;
    const int aCol = (tid & 3) * 4;
    const int bRow = tid >> 5;
    const int bCol = (tid & 31) * 4;
    const int tr = (tid >> 4) * 8;
    const int tc = (tid & 15) * 8;

    const float* Ablk = A + (size_t)br * 128 * K;
    const float* Wblk = W + bc * 128;

    float acc[8][8];
#pragma unroll
    for (int i = 0; i < 8; i++)
#pragma unroll
        for (int j = 0; j < 8; j++) acc[i][j] = 0.0f;

    for (int k0 = 0; k0 < K; k0 += 16) {
        float4 a0 = *reinterpret_cast<const float4*>(Ablk + (size_t)aRow * K + k0 + aCol);
        float4 a1 = *reinterpret_cast<const float4*>(Ablk + (size_t)(aRow + 64) * K + k0 + aCol);
        As[aCol + 0][aRow] = a0.x; As[aCol + 1][aRow] = a0.y;
        As[aCol + 2][aRow] = a0.z; As[aCol + 3][aRow] = a0.w;
        As[aCol + 0][aRow + 64] = a1.x; As[aCol + 1][aRow + 64] = a1.y;
        As[aCol + 2][aRow + 64] = a1.z; As[aCol + 3][aRow + 64] = a1.w;
        *reinterpret_cast<float4*>(&Bs[bRow][bCol]) =
            *reinterpret_cast<const float4*>(Wblk + (size_t)(k0 + bRow) * Nn + bCol);
        *reinterpret_cast<float4*>(&Bs[bRow + 8][bCol]) =
            *reinterpret_cast<const float4*>(Wblk + (size_t)(k0 + bRow + 8) * Nn + bCol);
        __syncthreads();
#pragma unroll
        for (int kk = 0; kk < 16; kk++) {
            float ar[8], bb[8];
#pragma unroll
            for (int i = 0; i < 8; i++) ar[i] = As[kk][tr + i];
#pragma unroll
            for (int j = 0; j < 8; j++) bb[j] = Bs[kk][tc + j];
#pragma unroll
            for (int i = 0; i < 8; i++)
#pragma unroll
                for (int j = 0; j < 8; j++) acc[i][j] += ar[i] * bb[j];
        }
        __syncthreads();
    }

    float cb[8], cs[8], csh[8];
#pragma unroll
    for (int j = 0; j < 8; j++) {
        int col = bc * 128 + tc + j;
        cb[j] = (EPI != 0) ? bias[col] : 0.0f;
        if (EPI == 1) {
            float s = ga[col] * rsqrtf(va[col] + BN_EPS);
            cs[j] = s;
            csh[j] = be[col] - mu[col] * s;
        } else {
            cs[j] = 1.0f;
            csh[j] = 0.0f;
        }
    }

#pragma unroll
    for (int i = 0; i < 8; i++) {
        int row = br * 128 + tr + i;
        float* Crow = C + (size_t)row * Nn + bc * 128 + tc;
        float vals[8];
#pragma unroll
        for (int j = 0; j < 8; j++) {
            float v = acc[i][j];
            if (EPI != 0) v += cb[j];
            if (EPI == 1 || EPI == 2) v = fmaxf(v, 0.0f);
            if (EPI == 1) v = v * cs[j] + csh[j];
            vals[j] = v;
        }
        *reinterpret_cast<float4*>(Crow + 0) = make_float4(vals[0], vals[1], vals[2], vals[3]);
        *reinterpret_cast<float4*>(Crow + 4) = make_float4(vals[4], vals[5], vals[6], vals[7]);
    }
}

// ---------------- launch -----------------------------------------------------
extern "C" void kernel_launch(void* const* d_in, const int* in_sizes, int n_in,
                              void* d_out, int out_size) {
    const float* x   = (const float*)d_in[0];
    const int* ei    = (const int*)d_in[1];
    const int* batch = (const int*)d_in[2];
    const float* W1  = (const float*)d_in[3];  const float* b1  = (const float*)d_in[4];
    const float* W2  = (const float*)d_in[5];  const float* b2  = (const float*)d_in[6];
    const float* W3  = (const float*)d_in[7];  const float* b3  = (const float*)d_in[8];
    const float* g1  = (const float*)d_in[9];  const float* be1 = (const float*)d_in[10];
    const float* m1  = (const float*)d_in[11]; const float* v1  = (const float*)d_in[12];
    const float* g2  = (const float*)d_in[13]; const float* be2 = (const float*)d_in[14];
    const float* m2  = (const float*)d_in[15]; const float* v2  = (const float*)d_in[16];
    const float* g3  = (const float*)d_in[17]; const float* be3 = (const float*)d_in[18];
    const float* m3  = (const float*)d_in[19]; const float* v3  = (const float*)d_in[20];
    const float* Wf1 = (const float*)d_in[21]; const float* bf1 = (const float*)d_in[22];
    const float* Wf2 = (const float*)d_in[23]; const float* bf2 = (const float*)d_in[24];
    float* out = (float*)d_out;

    const int* src = ei;
    const int* dst = ei + CE;

    float *dinv, *cw, *agg1, *h1, *t2, *a2, *t3, *a3, *pool, *mlp1, *bns, *bnsh;
    int *cnt, *noff, *cur, *bsum, *csrc, *gcnt, *goff, *gbsum;
    cudaGetSymbolAddress((void**)&dinv, g_dinv);
    cudaGetSymbolAddress((void**)&cnt,  g_cnt);
    cudaGetSymbolAddress((void**)&noff, g_noff);
    cudaGetSymbolAddress((void**)&cur,  g_cur);
    cudaGetSymbolAddress((void**)&bsum, g_bsum);
    cudaGetSymbolAddress((void**)&csrc, g_csrc);
    cudaGetSymbolAddress((void**)&cw,   g_cw);
    cudaGetSymbolAddress((void**)&gcnt, g_gcnt);
    cudaGetSymbolAddress((void**)&goff, g_goff);
    cudaGetSymbolAddress((void**)&gbsum, g_gbsum);
    cudaGetSymbolAddress((void**)&bns,  g_bns);
    cudaGetSymbolAddress((void**)&bnsh, g_bnsh);
    cudaGetSymbolAddress((void**)&agg1, g_agg1);
    cudaGetSymbolAddress((void**)&h1,   g_h1);
    cudaGetSymbolAddress((void**)&t2,   g_t2);
    cudaGetSymbolAddress((void**)&a2,   g_a2);
    cudaGetSymbolAddress((void**)&t3,   g_t3);
    cudaGetSymbolAddress((void**)&a3,   g_a3);
    cudaGetSymbolAddress((void**)&pool, g_pool);
    cudaGetSymbolAddress((void**)&mlp1, g_mlp1);

    const int T = 256;

    // ---- CSR build ----
    k_zero_i<<<(CN + T - 1) / T, T>>>(cnt, CN);
    k_zero_i<<<(CN + T - 1) / T, T>>>(cur, CN);
    k_zero_i<<<(CG + T - 1) / T, T>>>(gcnt, CG);
    k_hist<<<(CE + T - 1) / T, T>>>(dst, CE, cnt);
    k_hist<<<(CN + T - 1) / T, T>>>(batch, CN, gcnt);
    k_dinv_from_cnt<<<(CN + T - 1) / T, T>>>(cnt, dinv);
    k_scan_block<<<CN / 256, 256>>>(cnt, noff, bsum, CN);
    k_scan_partials<<<1, 1024>>>(bsum, CN / 256);
    k_scan_add<<<(CN + T - 1) / T, T>>>(noff, bsum, CN, CE);
    k_scan_block<<<CG / 256, 256>>>(gcnt, goff, gbsum, CG);
    k_scan_partials<<<1, 1024>>>(gbsum, CG / 256);
    k_scan_add<<<(CG + T - 1) / T, T>>>(goff, gbsum, CG, CN);
    k_csr_scatter<<<(CE + T - 1) / T, T>>>(src, dst, dinv, noff, cur, csrc, cw);

    // ---- BN constants for layers 2 & 3 ----
    k_bnprep<<<(DH + T - 1) / T, T>>>(g2, be2, m2, v2, bns, bnsh, DH);
    k_bnprep<<<(DOUTD + T - 1) / T, T>>>(g3, be3, m3, v3, bns + DH, bnsh + DH, DOUTD);

    // ---- layer 1: aggregate first (D=128), then GEMM with fused bias+relu+BN ----
    k_agg_csr<DIN, false><<<CN / 4, 128>>>(x, agg1, noff, csrc, cw, dinv,
                                           nullptr, nullptr, nullptr);
    {
        dim3 grid(DH / 128, CN / 128);
        k_sgemm<1><<<grid, 256>>>(agg1, W1, h1, CN, DIN, DH, b1, g1, be1, m1, v1);
    }

    // ---- layer 2: GEMM, then aggregate (D=512) with fused bias+relu+BN ----
    {
        dim3 grid(DH / 128, CN / 128);
        k_sgemm<0><<<grid, 256>>>(h1, W2, t2, CN, DH, DH, nullptr, nullptr, nullptr, nullptr, nullptr);
    }
    k_agg_csr<DH, true><<<CN, 128>>>(t2, a2, noff, csrc, cw, dinv, b2, bns, bnsh);

    // ---- layer 3: GEMM, then aggregate (D=256) with fused bias+relu+BN ----
    {
        dim3 grid(DOUTD / 128, CN / 128);
        k_sgemm<0><<<grid, 256>>>(a2, W3, t3, CN, DH, DOUTD, nullptr, nullptr, nullptr, nullptr, nullptr);
    }
    k_agg_csr<DOUTD, true><<<CN / 2, 128>>>(t3, a3, noff, csrc, cw, dinv,
                                            b3, bns + DH, bnsh + DH);

    // ---- segment mean pool ----
    k_pool_seg<<<CG / 2, 128>>>(a3, goff, pool);

    // ---- MLP head ----
    {
        dim3 grid(DOUTD / 128, CG / 128);
        k_sgemm<2><<<grid, 256>>>(pool, Wf1, mlp1, CG, DOUTD, DOUTD, bf1, nullptr, nullptr, nullptr, nullptr);
        k_sgemm<3><<<grid, 256>>>(mlp1, Wf2, out, CG, DOUTD, DOUTD, bf2, nullptr, nullptr, nullptr, nullptr);
    }
}

// round 3
// speedup vs baseline: 2.6858x; 1.8118x over previous
#include <cuda_runtime.h>
#include <math.h>
#include <stdint.h>

#define CN 131072
#define CE 524288
#define CG 4096
#define DIN 128
#define DH  512
#define DOUTD 256
#define BN_EPS 1e-5f

// ---------------- scratch (static device globals; no allocation) -------------
__device__ float g_dinv[CN];
__device__ int   g_cnt [CN];
__device__ int   g_noff[CN + 1];
__device__ int   g_cur [CN];
__device__ int   g_bsum[512];
__device__ int   g_csrc[CE];
__device__ float g_cw  [CE];
__device__ int   g_gcnt[CG];
__device__ int   g_goff[CG + 1];
__device__ int   g_gbsum[16];
__device__ float g_bns [DH + DOUTD];
__device__ float g_bnsh[DH + DOUTD];
__device__ float g_agg1[(size_t)CN * DIN];
__device__ float g_h1  [(size_t)CN * DH];
__device__ float g_t2  [(size_t)CN * DH];
__device__ float g_a2  [(size_t)CN * DH];
__device__ float g_t3  [(size_t)CN * DOUTD];
__device__ float g_a3  [(size_t)CN * DOUTD];
__device__ float g_pool[(size_t)CG * DOUTD];
__device__ float g_mlp1[(size_t)CG * DOUTD];

// ---------------- small utility kernels --------------------------------------
__global__ void k_zero_i(int* __restrict__ p, int n) {
    unsigned i = blockIdx.x * blockDim.x + threadIdx.x;
    if (i < (unsigned)n) p[i] = 0;
}

__global__ void k_hist(const int* __restrict__ keys, int n, int* __restrict__ cnt) {
    unsigned i = blockIdx.x * blockDim.x + threadIdx.x;
    if (i < (unsigned)n) atomicAdd(&cnt[keys[i]], 1);
}

__global__ void k_dinv_from_cnt(const int* __restrict__ cnt, float* __restrict__ dinv) {
    unsigned i = blockIdx.x * blockDim.x + threadIdx.x;
    if (i < CN) dinv[i] = rsqrtf((float)(cnt[i] + 1));
}

__global__ void k_scan_block(const int* __restrict__ in, int* __restrict__ out,
                             int* __restrict__ bsum, int n) {
    __shared__ int sh[256];
    int t = threadIdx.x;
    int i = blockIdx.x * 256 + t;
    int v = (i < n) ? in[i] : 0;
    sh[t] = v; __syncthreads();
#pragma unroll
    for (int o = 1; o < 256; o <<= 1) {
        int x = (t >= o) ? sh[t - o] : 0;
        __syncthreads();
        sh[t] += x;
        __syncthreads();
    }
    if (i < n) out[i] = sh[t] - v;
    if (t == 255) bsum[blockIdx.x] = sh[255];
}

__global__ void k_scan_partials(int* __restrict__ bsum, int nb) {
    __shared__ int sh[1024];
    int t = threadIdx.x;
    int v = (t < nb) ? bsum[t] : 0;
    sh[t] = v; __syncthreads();
#pragma unroll
    for (int o = 1; o < 1024; o <<= 1) {
        int x = (t >= o) ? sh[t - o] : 0;
        __syncthreads();
        sh[t] += x;
        __syncthreads();
    }
    if (t < nb) bsum[t] = sh[t] - v;
}

__global__ void k_scan_add(int* __restrict__ out, const int* __restrict__ bsum,
                           int n, int total) {
    unsigned i = blockIdx.x * blockDim.x + threadIdx.x;
    if (i < (unsigned)n) out[i] += bsum[i >> 8];
    if (i == 0) out[n] = total;
}

__global__ void k_csr_scatter(const int* __restrict__ src, const int* __restrict__ dst,
                              const float* __restrict__ dinv,
                              const int* __restrict__ noff, int* __restrict__ cur,
                              int* __restrict__ csrc, float* __restrict__ cw) {
    unsigned e = blockIdx.x * blockDim.x + threadIdx.x;
    if (e >= CE) return;
    int d = dst[e], s = src[e];
    int pos = noff[d] + atomicAdd(&cur[d], 1);
    csrc[pos] = s;
    cw[pos] = dinv[s] * dinv[d];
}

__global__ void k_bnprep(const float* __restrict__ g, const float* __restrict__ be,
                         const float* __restrict__ m, const float* __restrict__ v,
                         float* __restrict__ s, float* __restrict__ sh, int n) {
    unsigned i = blockIdx.x * blockDim.x + threadIdx.x;
    if (i >= (unsigned)n) return;
    float sc = g[i] * rsqrtf(v[i] + BN_EPS);
    s[i] = sc;
    sh[i] = be[i] - m[i] * sc;
}

// ---------------- CSR aggregation (gather, no atomics) ------------------------
template <int D, bool BN>
__global__ __launch_bounds__(128) void k_agg_csr(
    const float* __restrict__ t, float* __restrict__ out,
    const int* __restrict__ noff, const int* __restrict__ csrc,
    const float* __restrict__ cw, const float* __restrict__ dinv,
    const float* __restrict__ bias, const float* __restrict__ bns,
    const float* __restrict__ bnsh) {
    constexpr int TPN = D / 4;
    constexpr int NPB = 128 / TPN;
    int node = blockIdx.x * NPB + threadIdx.x / TPN;
    int lane = threadIdx.x % TPN;
    int c = lane * 4;

    float di = dinv[node];
    float4 acc = *reinterpret_cast<const float4*>(t + (size_t)node * D + c);
    float w0 = di * di;
    acc.x *= w0; acc.y *= w0; acc.z *= w0; acc.w *= w0;

    int beg = noff[node], end = noff[node + 1];
    for (int p = beg; p < end; p++) {
        int s = csrc[p];
        float w = cw[p];
        float4 v = *reinterpret_cast<const float4*>(t + (size_t)s * D + c);
        acc.x += v.x * w; acc.y += v.y * w; acc.z += v.z * w; acc.w += v.w * w;
    }
    if (BN) {
        float4 b = *reinterpret_cast<const float4*>(bias + c);
        float4 s4 = *reinterpret_cast<const float4*>(bns + c);
        float4 h4 = *reinterpret_cast<const float4*>(bnsh + c);
        acc.x = fmaxf(acc.x + b.x, 0.0f) * s4.x + h4.x;
        acc.y = fmaxf(acc.y + b.y, 0.0f) * s4.y + h4.y;
        acc.z = fmaxf(acc.z + b.z, 0.0f) * s4.z + h4.z;
        acc.w = fmaxf(acc.w + b.w, 0.0f) * s4.w + h4.w;
    }
    *reinterpret_cast<float4*>(out + (size_t)node * D + c) = acc;
}

// ---------------- segment mean pool ------------------------------------------
__global__ __launch_bounds__(128) void k_pool_seg(const float* __restrict__ h,
                                                  const int* __restrict__ goff,
                                                  float* __restrict__ pooled) {
    int g = blockIdx.x * 2 + threadIdx.x / 64;
    int lane = threadIdx.x % 64;
    int c = lane * 4;
    int beg = goff[g], end = goff[g + 1];
    float4 acc = make_float4(0.f, 0.f, 0.f, 0.f);
    for (int n = beg; n < end; n++) {
        float4 v = *reinterpret_cast<const float4*>(h + (size_t)n * DOUTD + c);
        acc.x += v.x; acc.y += v.y; acc.z += v.z; acc.w += v.w;
    }
    float inv = 1.0f / fmaxf((float)(end - beg), 1.0f);
    acc.x *= inv; acc.y *= inv; acc.z *= inv; acc.w *= inv;
    *reinterpret_cast<float4*>(pooled + (size_t)g * DOUTD + c) = acc;
}

// ---------------- TF32 tensor-core GEMM --------------------------------------
// C[M,Nn] = A[M,K] @ W[K,Nn] (+ epilogue). M%128==0, Nn%128==0, K%32==0.
// Block 128x128, 256 thr = 8 warps (2 x 4), warp tile 64x32, mma m16n8k8.
__device__ __forceinline__ uint32_t f2tf(float f) {
    uint32_t u;
    asm("cvt.rna.tf32.f32 %0, %1;" : "=r"(u) : "f"(f));
    return u;
}

__device__ __forceinline__ void mma_tf32(float* c, const uint32_t* a, const uint32_t* b) {
    asm volatile(
        "mma.sync.aligned.m16n8k8.row.col.f32.tf32.tf32.f32 "
        "{%0,%1,%2,%3}, {%4,%5,%6,%7}, {%8,%9}, {%0,%1,%2,%3};"
        : "+f"(c[0]), "+f"(c[1]), "+f"(c[2]), "+f"(c[3])
        : "r"(a[0]), "r"(a[1]), "r"(a[2]), "r"(a[3]), "r"(b[0]), "r"(b[1]));
}

// EPI: 0=none, 1=bias+relu+BN(precomputed s,sh), 2=bias+relu, 3=bias
template <int EPI>
__global__ __launch_bounds__(256) void k_tf32gemm(
    const float* __restrict__ A, const float* __restrict__ W, float* __restrict__ C,
    int M, int K, int Nn,
    const float* __restrict__ bias, const float* __restrict__ bns,
    const float* __restrict__ bnsh) {
    __shared__ uint32_t As[32][132];   // [k][m], pad -> stride 132 (==4 mod 32)
    __shared__ uint32_t Bs[32][132];   // [k][n]

    const int tid = threadIdx.x;
    const int bc = blockIdx.x, br = blockIdx.y;
    const int lane = tid & 31;
    const int wid = tid >> 5;
    const int wm = (wid >> 2) * 64;    // warp row offset in tile
    const int wn = (wid & 3) * 32;     // warp col offset in tile

    // A load mapping: row = tid/2, k = (tid&1)*4 + i*8 + j
    const int arow = tid >> 1;
    const int ak = (tid & 1) * 4;
    // B load mapping: n4 = (tid&31)*4, k = tid/32 + i*8
    const int bn4 = (tid & 31) * 4;
    const int bk = tid >> 5;

    const float* Abase = A + (size_t)(br * 128 + arow) * K + ak;
    const float* Wbase = W + (size_t)bk * Nn + bc * 128 + bn4;

    float acc[4][4][4];
#pragma unroll
    for (int mf = 0; mf < 4; mf++)
#pragma unroll
        for (int nf = 0; nf < 4; nf++)
#pragma unroll
            for (int r = 0; r < 4; r++) acc[mf][nf][r] = 0.0f;

    for (int k0 = 0; k0 < K; k0 += 32) {
        // fill As (transposed)
#pragma unroll
        for (int i = 0; i < 4; i++) {
            float4 v = *reinterpret_cast<const float4*>(Abase + k0 + i * 8);
            int kk = ak + i * 8;
            As[kk + 0][arow] = f2tf(v.x);
            As[kk + 1][arow] = f2tf(v.y);
            As[kk + 2][arow] = f2tf(v.z);
            As[kk + 3][arow] = f2tf(v.w);
        }
        // fill Bs
#pragma unroll
        for (int i = 0; i < 4; i++) {
            float4 v = *reinterpret_cast<const float4*>(Wbase + (size_t)(k0 + i * 8) * Nn);
            uint4 u;
            u.x = f2tf(v.x); u.y = f2tf(v.y); u.z = f2tf(v.z); u.w = f2tf(v.w);
            *reinterpret_cast<uint4*>(&Bs[bk + i * 8][bn4]) = u;
        }
        __syncthreads();

        const int gr = lane >> 2;      // 0..7
        const int gc = lane & 3;       // 0..3
#pragma unroll
        for (int ks = 0; ks < 32; ks += 8) {
            uint32_t af[4][4];
#pragma unroll
            for (int mf = 0; mf < 4; mf++) {
                int mb = wm + mf * 16;
                af[mf][0] = As[ks + gc][mb + gr];
                af[mf][1] = As[ks + gc][mb + gr + 8];
                af[mf][2] = As[ks + gc + 4][mb + gr];
                af[mf][3] = As[ks + gc + 4][mb + gr + 8];
            }
            uint32_t bf[4][2];
#pragma unroll
            for (int nf = 0; nf < 4; nf++) {
                int nb = wn + nf * 8;
                bf[nf][0] = Bs[ks + gc][nb + gr];
                bf[nf][1] = Bs[ks + gc + 4][nb + gr];
            }
#pragma unroll
            for (int mf = 0; mf < 4; mf++)
#pragma unroll
                for (int nf = 0; nf < 4; nf++)
                    mma_tf32(acc[mf][nf], af[mf], bf[nf]);
        }
        __syncthreads();
    }

    // epilogue + store
    const int gr = lane >> 2;
    const int gc = lane & 3;
#pragma unroll
    for (int nf = 0; nf < 4; nf++) {
        int col = bc * 128 + wn + nf * 8 + gc * 2;
        float b0 = 0.f, b1 = 0.f, s0 = 1.f, s1 = 1.f, h0 = 0.f, h1 = 0.f;
        if (EPI != 0) { b0 = bias[col]; b1 = bias[col + 1]; }
        if (EPI == 1) {
            s0 = bns[col]; s1 = bns[col + 1];
            h0 = bnsh[col]; h1 = bnsh[col + 1];
        }
#pragma unroll
        for (int mf = 0; mf < 4; mf++) {
            int row0 = br * 128 + wm + mf * 16 + gr;
            float v0 = acc[mf][nf][0], v1 = acc[mf][nf][1];
            float v2 = acc[mf][nf][2], v3 = acc[mf][nf][3];
            if (EPI != 0) { v0 += b0; v1 += b1; v2 += b0; v3 += b1; }
            if (EPI == 1 || EPI == 2) {
                v0 = fmaxf(v0, 0.f); v1 = fmaxf(v1, 0.f);
                v2 = fmaxf(v2, 0.f); v3 = fmaxf(v3, 0.f);
            }
            if (EPI == 1) {
                v0 = v0 * s0 + h0; v1 = v1 * s1 + h1;
                v2 = v2 * s0 + h0; v3 = v3 * s1 + h1;
            }
            *reinterpret_cast<float2*>(C + (size_t)row0 * Nn + col) = make_float2(v0, v1);
            *reinterpret_cast<float2*>(C + (size_t)(row0 + 8) * Nn + col) = make_float2(v2, v3);
        }
    }
}

// ---------------- launch -----------------------------------------------------
extern "C" void kernel_launch(void* const* d_in, const int* in_sizes, int n_in,
                              void* d_out, int out_size) {
    const float* x   = (const float*)d_in[0];
    const int* ei    = (const int*)d_in[1];
    const int* batch = (const int*)d_in[2];
    const float* W1  = (const float*)d_in[3];  const float* b1  = (const float*)d_in[4];
    const float* W2  = (const float*)d_in[5];  const float* b2  = (const float*)d_in[6];
    const float* W3  = (const float*)d_in[7];  const float* b3  = (const float*)d_in[8];
    const float* g1  = (const float*)d_in[9];  const float* be1 = (const float*)d_in[10];
    const float* m1  = (const float*)d_in[11]; const float* v1  = (const float*)d_in[12];
    const float* g2  = (const float*)d_in[13]; const float* be2 = (const float*)d_in[14];
    const float* m2  = (const float*)d_in[15]; const float* v2  = (const float*)d_in[16];
    const float* g3  = (const float*)d_in[17]; const float* be3 = (const float*)d_in[18];
    const float* m3  = (const float*)d_in[19]; const float* v3  = (const float*)d_in[20];
    const float* Wf1 = (const float*)d_in[21]; const float* bf1 = (const float*)d_in[22];
    const float* Wf2 = (const float*)d_in[23]; const float* bf2 = (const float*)d_in[24];
    float* out = (float*)d_out;

    const int* src = ei;
    const int* dst = ei + CE;

    float *dinv, *cw, *agg1, *h1, *t2, *a2, *t3, *a3, *pool, *mlp1, *bns, *bnsh;
    int *cnt, *noff, *cur, *bsum, *csrc, *gcnt, *goff, *gbsum;
    cudaGetSymbolAddress((void**)&dinv, g_dinv);
    cudaGetSymbolAddress((void**)&cnt,  g_cnt);
    cudaGetSymbolAddress((void**)&noff, g_noff);
    cudaGetSymbolAddress((void**)&cur,  g_cur);
    cudaGetSymbolAddress((void**)&bsum, g_bsum);
    cudaGetSymbolAddress((void**)&csrc, g_csrc);
    cudaGetSymbolAddress((void**)&cw,   g_cw);
    cudaGetSymbolAddress((void**)&gcnt, g_gcnt);
    cudaGetSymbolAddress((void**)&goff, g_goff);
    cudaGetSymbolAddress((void**)&gbsum, g_gbsum);
    cudaGetSymbolAddress((void**)&bns,  g_bns);
    cudaGetSymbolAddress((void**)&bnsh, g_bnsh);
    cudaGetSymbolAddress((void**)&agg1, g_agg1);
    cudaGetSymbolAddress((void**)&h1,   g_h1);
    cudaGetSymbolAddress((void**)&t2,   g_t2);
    cudaGetSymbolAddress((void**)&a2,   g_a2);
    cudaGetSymbolAddress((void**)&t3,   g_t3);
    cudaGetSymbolAddress((void**)&a3,   g_a3);
    cudaGetSymbolAddress((void**)&pool, g_pool);
    cudaGetSymbolAddress((void**)&mlp1, g_mlp1);

    const int T = 256;

    // ---- CSR build ----
    k_zero_i<<<(CN + T - 1) / T, T>>>(cnt, CN);
    k_zero_i<<<(CN + T - 1) / T, T>>>(cur, CN);
    k_zero_i<<<(CG + T - 1) / T, T>>>(gcnt, CG);
    k_hist<<<(CE + T - 1) / T, T>>>(dst, CE, cnt);
    k_hist<<<(CN + T - 1) / T, T>>>(batch, CN, gcnt);
    k_dinv_from_cnt<<<(CN + T - 1) / T, T>>>(cnt, dinv);
    k_scan_block<<<CN / 256, 256>>>(cnt, noff, bsum, CN);
    k_scan_partials<<<1, 1024>>>(bsum, CN / 256);
    k_scan_add<<<(CN + T - 1) / T, T>>>(noff, bsum, CN, CE);
    k_scan_block<<<CG / 256, 256>>>(gcnt, goff, gbsum, CG);
    k_scan_partials<<<1, 1024>>>(gbsum, CG / 256);
    k_scan_add<<<(CG + T - 1) / T, T>>>(goff, gbsum, CG, CN);
    k_csr_scatter<<<(CE + T - 1) / T, T>>>(src, dst, dinv, noff, cur, csrc, cw);

    // ---- BN constants ----
    // layer1 BN consts live in the first GEMM epilogue: prep into bns/bnsh tail? No:
    // layer1 uses its own (DH) slot via a separate prep into the same arrays is fine
    // since layer1 GEMM consumes them before layer2 aggregation needs them... they
    // overlap (both DH). Use dedicated prep per use instead:
    // bns[0:DH]   = layer2 BN, bnsh same
    // bns[DH:DH+DOUTD] = layer3 BN
    // layer1 BN handled by prepping into a temporary region first and consuming it
    // immediately (GEMM1 runs before layer2 prep would be needed) -> order matters.
    // Simpler: prep layer1 consts into bns/bnsh[0:DH], run GEMM1, then re-prep for layer2.
    k_bnprep<<<(DH + T - 1) / T, T>>>(g1, be1, m1, v1, bns, bnsh, DH);

    // ---- layer 1: aggregate (D=128) then GEMM (bias+relu+BN fused) ----
    k_agg_csr<DIN, false><<<CN / 4, 128>>>(x, agg1, noff, csrc, cw, dinv,
                                           nullptr, nullptr, nullptr);
    {
        dim3 grid(DH / 128, CN / 128);
        k_tf32gemm<1><<<grid, 256>>>(agg1, W1, h1, CN, DIN, DH, b1, bns, bnsh);
    }

    // re-prep BN consts for layers 2 & 3
    k_bnprep<<<(DH + T - 1) / T, T>>>(g2, be2, m2, v2, bns, bnsh, DH);
    k_bnprep<<<(DOUTD + T - 1) / T, T>>>(g3, be3, m3, v3, bns + DH, bnsh + DH, DOUTD);

    // ---- layer 2: GEMM then aggregate (fused bias+relu+BN) ----
    {
        dim3 grid(DH / 128, CN / 128);
        k_tf32gemm<0><<<grid, 256>>>(h1, W2, t2, CN, DH, DH, nullptr, nullptr, nullptr);
    }
    k_agg_csr<DH, true><<<CN, 128>>>(t2, a2, noff, csrc, cw, dinv, b2, bns, bnsh);

    // ---- layer 3: GEMM then aggregate (fused bias+relu+BN) ----
    {
        dim3 grid(DOUTD / 128, CN / 128);
        k_tf32gemm<0><<<grid, 256>>>(a2, W3, t3, CN, DH, DOUTD, nullptr, nullptr, nullptr);
    }
    k_agg_csr<DOUTD, true><<<CN / 2, 128>>>(t3, a3, noff, csrc, cw, dinv,
                                            b3, bns + DH, bnsh + DH);

    // ---- segment mean pool ----
    k_pool_seg<<<CG / 2, 128>>>(a3, goff, pool);

    // ---- MLP head ----
    {
        dim3 grid(DOUTD / 128, CG / 128);
        k_tf32gemm<2><<<grid, 256>>>(pool, Wf1, mlp1, CG, DOUTD, DOUTD, bf1, nullptr, nullptr);
        k_tf32gemm<3><<<grid, 256>>>(mlp1, Wf2, out, CG, DOUTD, DOUTD, bf2, nullptr, nullptr);
    }
}

// round 4
// speedup vs baseline: 3.1446x; 1.1708x over previous
#include <cuda_runtime.h>
#include <math.h>
#include <stdint.h>

#define CN 131072
#define CE 524288
#define CG 4096
#define DIN 128
#define DH  512
#define DOUTD 256
#define BN_EPS 1e-5f

// ---------------- scratch (static device globals; no allocation) -------------
__device__ float g_dinv[CN];
__device__ int   g_cnt [CN];
__device__ int   g_noff[CN + 1];
__device__ int   g_cur [CN];
__device__ int   g_bsum[512];
__device__ int   g_csrc[CE];
__device__ float g_cw  [CE];
__device__ int   g_gcnt[CG];
__device__ int   g_goff[CG + 1];
__device__ int   g_gbsum[16];
__device__ float g_bns [DH + DOUTD];
__device__ float g_bnsh[DH + DOUTD];
__device__ float g_agg1[(size_t)CN * DIN];
__device__ float g_h1  [(size_t)CN * DH];
__device__ float g_t2  [(size_t)CN * DH];
__device__ float g_a2  [(size_t)CN * DH];
__device__ float g_t3  [(size_t)CN * DOUTD];
__device__ float g_a3  [(size_t)CN * DOUTD];
__device__ float g_pool[(size_t)CG * DOUTD];
__device__ float g_mlp1[(size_t)CG * DOUTD];

// ---------------- small utility kernels --------------------------------------
__global__ void k_zero_i(int* __restrict__ p, int n) {
    unsigned i = blockIdx.x * blockDim.x + threadIdx.x;
    if (i < (unsigned)n) p[i] = 0;
}

__global__ void k_hist(const int* __restrict__ keys, int n, int* __restrict__ cnt) {
    unsigned i = blockIdx.x * blockDim.x + threadIdx.x;
    if (i < (unsigned)n) atomicAdd(&cnt[keys[i]], 1);
}

__global__ void k_dinv_from_cnt(const int* __restrict__ cnt, float* __restrict__ dinv) {
    unsigned i = blockIdx.x * blockDim.x + threadIdx.x;
    if (i < CN) dinv[i] = rsqrtf((float)(cnt[i] + 1));
}

__global__ void k_scan_block(const int* __restrict__ in, int* __restrict__ out,
                             int* __restrict__ bsum, int n) {
    __shared__ int sh[256];
    int t = threadIdx.x;
    int i = blockIdx.x * 256 + t;
    int v = (i < n) ? in[i] : 0;
    sh[t] = v; __syncthreads();
#pragma unroll
    for (int o = 1; o < 256; o <<= 1) {
        int x = (t >= o) ? sh[t - o] : 0;
        __syncthreads();
        sh[t] += x;
        __syncthreads();
    }
    if (i < n) out[i] = sh[t] - v;
    if (t == 255) bsum[blockIdx.x] = sh[255];
}

__global__ void k_scan_partials(int* __restrict__ bsum, int nb) {
    __shared__ int sh[1024];
    int t = threadIdx.x;
    int v = (t < nb) ? bsum[t] : 0;
    sh[t] = v; __syncthreads();
#pragma unroll
    for (int o = 1; o < 1024; o <<= 1) {
        int x = (t >= o) ? sh[t - o] : 0;
        __syncthreads();
        sh[t] += x;
        __syncthreads();
    }
    if (t < nb) bsum[t] = sh[t] - v;
}

__global__ void k_scan_add(int* __restrict__ out, const int* __restrict__ bsum,
                           int n, int total) {
    unsigned i = blockIdx.x * blockDim.x + threadIdx.x;
    if (i < (unsigned)n) out[i] += bsum[i >> 8];
    if (i == 0) out[n] = total;
}

__global__ void k_csr_scatter(const int* __restrict__ src, const int* __restrict__ dst,
                              const float* __restrict__ dinv,
                              const int* __restrict__ noff, int* __restrict__ cur,
                              int* __restrict__ csrc, float* __restrict__ cw) {
    unsigned e = blockIdx.x * blockDim.x + threadIdx.x;
    if (e >= CE) return;
    int d = dst[e], s = src[e];
    int pos = noff[d] + atomicAdd(&cur[d], 1);
    csrc[pos] = s;
    cw[pos] = dinv[s] * dinv[d];
}

__global__ void k_bnprep(const float* __restrict__ g, const float* __restrict__ be,
                         const float* __restrict__ m, const float* __restrict__ v,
                         float* __restrict__ s, float* __restrict__ sh, int n) {
    unsigned i = blockIdx.x * blockDim.x + threadIdx.x;
    if (i >= (unsigned)n) return;
    float sc = g[i] * rsqrtf(v[i] + BN_EPS);
    s[i] = sc;
    sh[i] = be[i] - m[i] * sc;
}

// ---------------- CSR aggregation (gather, no atomics) ------------------------
template <int D, bool BN>
__global__ __launch_bounds__(128) void k_agg_csr(
    const float* __restrict__ t, float* __restrict__ out,
    const int* __restrict__ noff, const int* __restrict__ csrc,
    const float* __restrict__ cw, const float* __restrict__ dinv,
    const float* __restrict__ bias, const float* __restrict__ bns,
    const float* __restrict__ bnsh) {
    constexpr int TPN = D / 4;
    constexpr int NPB = 128 / TPN;
    int node = blockIdx.x * NPB + threadIdx.x / TPN;
    int lane = threadIdx.x % TPN;
    int c = lane * 4;

    float di = dinv[node];
    float4 acc = *reinterpret_cast<const float4*>(t + (size_t)node * D + c);
    float w0 = di * di;
    acc.x *= w0; acc.y *= w0; acc.z *= w0; acc.w *= w0;

    int beg = noff[node], end = noff[node + 1];
    for (int p = beg; p < end; p++) {
        int s = csrc[p];
        float w = cw[p];
        float4 v = *reinterpret_cast<const float4*>(t + (size_t)s * D + c);
        acc.x += v.x * w; acc.y += v.y * w; acc.z += v.z * w; acc.w += v.w * w;
    }
    if (BN) {
        float4 b = *reinterpret_cast<const float4*>(bias + c);
        float4 s4 = *reinterpret_cast<const float4*>(bns + c);
        float4 h4 = *reinterpret_cast<const float4*>(bnsh + c);
        acc.x = fmaxf(acc.x + b.x, 0.0f) * s4.x + h4.x;
        acc.y = fmaxf(acc.y + b.y, 0.0f) * s4.y + h4.y;
        acc.z = fmaxf(acc.z + b.z, 0.0f) * s4.z + h4.z;
        acc.w = fmaxf(acc.w + b.w, 0.0f) * s4.w + h4.w;
    }
    *reinterpret_cast<float4*>(out + (size_t)node * D + c) = acc;
}

// ---------------- segment mean pool ------------------------------------------
__global__ __launch_bounds__(128) void k_pool_seg(const float* __restrict__ h,
                                                  const int* __restrict__ goff,
                                                  float* __restrict__ pooled) {
    int g = blockIdx.x * 2 + threadIdx.x / 64;
    int lane = threadIdx.x % 64;
    int c = lane * 4;
    int beg = goff[g], end = goff[g + 1];
    float4 acc = make_float4(0.f, 0.f, 0.f, 0.f);
    for (int n = beg; n < end; n++) {
        float4 v = *reinterpret_cast<const float4*>(h + (size_t)n * DOUTD + c);
        acc.x += v.x; acc.y += v.y; acc.z += v.z; acc.w += v.w;
    }
    float inv = 1.0f / fmaxf((float)(end - beg), 1.0f);
    acc.x *= inv; acc.y *= inv; acc.z *= inv; acc.w *= inv;
    *reinterpret_cast<float4*>(pooled + (size_t)g * DOUTD + c) = acc;
}

// ---------------- TF32 tensor-core GEMM (double-buffered) --------------------
// C[M,Nn] = A[M,K] @ W[K,Nn] (+ epilogue). M%128==0, Nn%128==0, K%16==0.
// Block 128x128, 256 thr = 8 warps (2 x 4), warp tile 64x32, mma m16n8k8.
// K-chunk 16, 2-stage smem pipeline with register staging.
// Smem stride 136: fragment bank = 8*gc + gr (bijective) -> conflict-free LDS.
__device__ __forceinline__ uint32_t f2tf(float f) {
    uint32_t u;
    asm("cvt.rna.tf32.f32 %0, %1;" : "=r"(u) : "f"(f));
    return u;
}

__device__ __forceinline__ void mma_tf32(float* c, const uint32_t* a, const uint32_t* b) {
    asm volatile(
        "mma.sync.aligned.m16n8k8.row.col.f32.tf32.tf32.f32 "
        "{%0,%1,%2,%3}, {%4,%5,%6,%7}, {%8,%9}, {%0,%1,%2,%3};"
        : "+f"(c[0]), "+f"(c[1]), "+f"(c[2]), "+f"(c[3])
        : "r"(a[0]), "r"(a[1]), "r"(a[2]), "r"(a[3]), "r"(b[0]), "r"(b[1]));
}

#define GSTRIDE 136

// EPI: 0=none, 1=bias+relu+BN(precomputed s,sh), 2=bias+relu, 3=bias
template <int EPI>
__global__ __launch_bounds__(256, 2) void k_tf32gemm(
    const float* __restrict__ A, const float* __restrict__ W, float* __restrict__ C,
    int M, int K, int Nn,
    const float* __restrict__ bias, const float* __restrict__ bns,
    const float* __restrict__ bnsh) {
    __shared__ uint32_t As[2][16][GSTRIDE];   // [buf][k][m]
    __shared__ uint32_t Bs[2][16][GSTRIDE];   // [buf][k][n]

    const int tid = threadIdx.x;
    const int bc = blockIdx.x, br = blockIdx.y;
    const int lane = tid & 31;
    const int wid = tid >> 5;
    const int wm = (wid >> 2) * 64;
    const int wn = (wid & 3) * 32;

    // A staging: row = tid/2 (0..127), k base = (tid&1)*8; two float4 (k..k+3, k+4..k+7)
    const int arow = tid >> 1;
    const int ak = (tid & 1) * 8;
    // B staging: rows brow, brow+8 (brow = tid/32), cols bn4..bn4+3
    const int bn4 = (tid & 31) * 4;
    const int brow = tid >> 5;

    const float* Aptr = A + (size_t)(br * 128 + arow) * K + ak;
    const float* Wptr = W + (size_t)brow * Nn + bc * 128 + bn4;
    const size_t WchunkStep = (size_t)16 * Nn;

    float acc[4][4][4];
#pragma unroll
    for (int mf = 0; mf < 4; mf++)
#pragma unroll
        for (int nf = 0; nf < 4; nf++)
#pragma unroll
            for (int r = 0; r < 4; r++) acc[mf][nf][r] = 0.0f;

    const int nchunks = K >> 4;

    float4 a0, a1, b0, b1;
    // prologue: load chunk 0 and store to buf 0
    a0 = *reinterpret_cast<const float4*>(Aptr);
    a1 = *reinterpret_cast<const float4*>(Aptr + 4);
    b0 = *reinterpret_cast<const float4*>(Wptr);
    b1 = *reinterpret_cast<const float4*>(Wptr + 8 * Nn);
    {
        As[0][ak + 0][arow] = f2tf(a0.x); As[0][ak + 1][arow] = f2tf(a0.y);
        As[0][ak + 2][arow] = f2tf(a0.z); As[0][ak + 3][arow] = f2tf(a0.w);
        As[0][ak + 4][arow] = f2tf(a1.x); As[0][ak + 5][arow] = f2tf(a1.y);
        As[0][ak + 6][arow] = f2tf(a1.z); As[0][ak + 7][arow] = f2tf(a1.w);
        uint4 u0, u1;
        u0.x = f2tf(b0.x); u0.y = f2tf(b0.y); u0.z = f2tf(b0.z); u0.w = f2tf(b0.w);
        u1.x = f2tf(b1.x); u1.y = f2tf(b1.y); u1.z = f2tf(b1.z); u1.w = f2tf(b1.w);
        *reinterpret_cast<uint4*>(&Bs[0][brow][bn4]) = u0;
        *reinterpret_cast<uint4*>(&Bs[0][brow + 8][bn4]) = u1;
    }
    __syncthreads();

    const int gr = lane >> 2;
    const int gc = lane & 3;

    for (int i = 0; i < nchunks; i++) {
        // issue global loads for chunk i+1 (latency hidden by the MMAs below)
        if (i + 1 < nchunks) {
            const float* Ap = Aptr + (i + 1) * 16;
            const float* Wp = Wptr + (size_t)(i + 1) * WchunkStep;
            a0 = *reinterpret_cast<const float4*>(Ap);
            a1 = *reinterpret_cast<const float4*>(Ap + 4);
            b0 = *reinterpret_cast<const float4*>(Wp);
            b1 = *reinterpret_cast<const float4*>(Wp + 8 * Nn);
        }

        // compute on buffer i&1
        const int cb = i & 1;
#pragma unroll
        for (int ks = 0; ks < 16; ks += 8) {
            uint32_t af[4][4];
#pragma unroll
            for (int mf = 0; mf < 4; mf++) {
                int mb = wm + mf * 16;
                af[mf][0] = As[cb][ks + gc][mb + gr];
                af[mf][1] = As[cb][ks + gc][mb + gr + 8];
                af[mf][2] = As[cb][ks + gc + 4][mb + gr];
                af[mf][3] = As[cb][ks + gc + 4][mb + gr + 8];
            }
            uint32_t bf[4][2];
#pragma unroll
            for (int nf = 0; nf < 4; nf++) {
                int nb = wn + nf * 8;
                bf[nf][0] = Bs[cb][ks + gc][nb + gr];
                bf[nf][1] = Bs[cb][ks + gc + 4][nb + gr];
            }
#pragma unroll
            for (int mf = 0; mf < 4; mf++)
#pragma unroll
                for (int nf = 0; nf < 4; nf++)
                    mma_tf32(acc[mf][nf], af[mf], bf[nf]);
        }

        // store chunk i+1 into the other buffer (safe: it was last read in
        // iteration i-1, protected by the barrier at the end of that iteration)
        if (i + 1 < nchunks) {
            const int nb2 = (i + 1) & 1;
            As[nb2][ak + 0][arow] = f2tf(a0.x); As[nb2][ak + 1][arow] = f2tf(a0.y);
            As[nb2][ak + 2][arow] = f2tf(a0.z); As[nb2][ak + 3][arow] = f2tf(a0.w);
            As[nb2][ak + 4][arow] = f2tf(a1.x); As[nb2][ak + 5][arow] = f2tf(a1.y);
            As[nb2][ak + 6][arow] = f2tf(a1.z); As[nb2][ak + 7][arow] = f2tf(a1.w);
            uint4 u0, u1;
            u0.x = f2tf(b0.x); u0.y = f2tf(b0.y); u0.z = f2tf(b0.z); u0.w = f2tf(b0.w);
            u1.x = f2tf(b1.x); u1.y = f2tf(b1.y); u1.z = f2tf(b1.z); u1.w = f2tf(b1.w);
            *reinterpret_cast<uint4*>(&Bs[nb2][brow][bn4]) = u0;
            *reinterpret_cast<uint4*>(&Bs[nb2][brow + 8][bn4]) = u1;
        }
        __syncthreads();
    }

    // epilogue + store
#pragma unroll
    for (int nf = 0; nf < 4; nf++) {
        int col = bc * 128 + wn + nf * 8 + gc * 2;
        float bb0 = 0.f, bb1 = 0.f, s0 = 1.f, s1 = 1.f, h0 = 0.f, h1 = 0.f;
        if (EPI != 0) { bb0 = bias[col]; bb1 = bias[col + 1]; }
        if (EPI == 1) {
            s0 = bns[col]; s1 = bns[col + 1];
            h0 = bnsh[col]; h1 = bnsh[col + 1];
        }
#pragma unroll
        for (int mf = 0; mf < 4; mf++) {
            int row0 = br * 128 + wm + mf * 16 + gr;
            float v0 = acc[mf][nf][0], v1 = acc[mf][nf][1];
            float v2 = acc[mf][nf][2], v3 = acc[mf][nf][3];
            if (EPI != 0) { v0 += bb0; v1 += bb1; v2 += bb0; v3 += bb1; }
            if (EPI == 1 || EPI == 2) {
                v0 = fmaxf(v0, 0.f); v1 = fmaxf(v1, 0.f);
                v2 = fmaxf(v2, 0.f); v3 = fmaxf(v3, 0.f);
            }
            if (EPI == 1) {
                v0 = v0 * s0 + h0; v1 = v1 * s1 + h1;
                v2 = v2 * s0 + h0; v3 = v3 * s1 + h1;
            }
            *reinterpret_cast<float2*>(C + (size_t)row0 * Nn + col) = make_float2(v0, v1);
            *reinterpret_cast<float2*>(C + (size_t)(row0 + 8) * Nn + col) = make_float2(v2, v3);
        }
    }
}

// ---------------- launch -----------------------------------------------------
extern "C" void kernel_launch(void* const* d_in, const int* in_sizes, int n_in,
                              void* d_out, int out_size) {
    const float* x   = (const float*)d_in[0];
    const int* ei    = (const int*)d_in[1];
    const int* batch = (const int*)d_in[2];
    const float* W1  = (const float*)d_in[3];  const float* b1  = (const float*)d_in[4];
    const float* W2  = (const float*)d_in[5];  const float* b2  = (const float*)d_in[6];
    const float* W3  = (const float*)d_in[7];  const float* b3  = (const float*)d_in[8];
    const float* g1  = (const float*)d_in[9];  const float* be1 = (const float*)d_in[10];
    const float* m1  = (const float*)d_in[11]; const float* v1  = (const float*)d_in[12];
    const float* g2  = (const float*)d_in[13]; const float* be2 = (const float*)d_in[14];
    const float* m2  = (const float*)d_in[15]; const float* v2  = (const float*)d_in[16];
    const float* g3  = (const float*)d_in[17]; const float* be3 = (const float*)d_in[18];
    const float* m3  = (const float*)d_in[19]; const float* v3  = (const float*)d_in[20];
    const float* Wf1 = (const float*)d_in[21]; const float* bf1 = (const float*)d_in[22];
    const float* Wf2 = (const float*)d_in[23]; const float* bf2 = (const float*)d_in[24];
    float* out = (float*)d_out;

    const int* src = ei;
    const int* dst = ei + CE;

    float *dinv, *cw, *agg1, *h1, *t2, *a2, *t3, *a3, *pool, *mlp1, *bns, *bnsh;
    int *cnt, *noff, *cur, *bsum, *csrc, *gcnt, *goff, *gbsum;
    cudaGetSymbolAddress((void**)&dinv, g_dinv);
    cudaGetSymbolAddress((void**)&cnt,  g_cnt);
    cudaGetSymbolAddress((void**)&noff, g_noff);
    cudaGetSymbolAddress((void**)&cur,  g_cur);
    cudaGetSymbolAddress((void**)&bsum, g_bsum);
    cudaGetSymbolAddress((void**)&csrc, g_csrc);
    cudaGetSymbolAddress((void**)&cw,   g_cw);
    cudaGetSymbolAddress((void**)&gcnt, g_gcnt);
    cudaGetSymbolAddress((void**)&goff, g_goff);
    cudaGetSymbolAddress((void**)&gbsum, g_gbsum);
    cudaGetSymbolAddress((void**)&bns,  g_bns);
    cudaGetSymbolAddress((void**)&bnsh, g_bnsh);
    cudaGetSymbolAddress((void**)&agg1, g_agg1);
    cudaGetSymbolAddress((void**)&h1,   g_h1);
    cudaGetSymbolAddress((void**)&t2,   g_t2);
    cudaGetSymbolAddress((void**)&a2,   g_a2);
    cudaGetSymbolAddress((void**)&t3,   g_t3);
    cudaGetSymbolAddress((void**)&a3,   g_a3);
    cudaGetSymbolAddress((void**)&pool, g_pool);
    cudaGetSymbolAddress((void**)&mlp1, g_mlp1);

    const int T = 256;

    // ---- CSR build ----
    k_zero_i<<<(CN + T - 1) / T, T>>>(cnt, CN);
    k_zero_i<<<(CN + T - 1) / T, T>>>(cur, CN);
    k_zero_i<<<(CG + T - 1) / T, T>>>(gcnt, CG);
    k_hist<<<(CE + T - 1) / T, T>>>(dst, CE, cnt);
    k_hist<<<(CN + T - 1) / T, T>>>(batch, CN, gcnt);
    k_dinv_from_cnt<<<(CN + T - 1) / T, T>>>(cnt, dinv);
    k_scan_block<<<CN / 256, 256>>>(cnt, noff, bsum, CN);
    k_scan_partials<<<1, 1024>>>(bsum, CN / 256);
    k_scan_add<<<(CN + T - 1) / T, T>>>(noff, bsum, CN, CE);
    k_scan_block<<<CG / 256, 256>>>(gcnt, goff, gbsum, CG);
    k_scan_partials<<<1, 1024>>>(gbsum, CG / 256);
    k_scan_add<<<(CG + T - 1) / T, T>>>(goff, gbsum, CG, CN);
    k_csr_scatter<<<(CE + T - 1) / T, T>>>(src, dst, dinv, noff, cur, csrc, cw);

    // ---- layer1 BN consts (consumed by GEMM1, then slots reused) ----
    k_bnprep<<<(DH + T - 1) / T, T>>>(g1, be1, m1, v1, bns, bnsh, DH);

    // ---- layer 1: aggregate (D=128) then GEMM (bias+relu+BN fused) ----
    k_agg_csr<DIN, false><<<CN / 4, 128>>>(x, agg1, noff, csrc, cw, dinv,
                                           nullptr, nullptr, nullptr);
    {
        dim3 grid(DH / 128, CN / 128);
        k_tf32gemm<1><<<grid, 256>>>(agg1, W1, h1, CN, DIN, DH, b1, bns, bnsh);
    }

    // re-prep BN consts for layers 2 & 3
    k_bnprep<<<(DH + T - 1) / T, T>>>(g2, be2, m2, v2, bns, bnsh, DH);
    k_bnprep<<<(DOUTD + T - 1) / T, T>>>(g3, be3, m3, v3, bns + DH, bnsh + DH, DOUTD);

    // ---- layer 2: GEMM then aggregate (fused bias+relu+BN) ----
    {
        dim3 grid(DH / 128, CN / 128);
        k_tf32gemm<0><<<grid, 256>>>(h1, W2, t2, CN, DH, DH, nullptr, nullptr, nullptr);
    }
    k_agg_csr<DH, true><<<CN, 128>>>(t2, a2, noff, csrc, cw, dinv, b2, bns, bnsh);

    // ---- layer 3: GEMM then aggregate (fused bias+relu+BN) ----
    {
        dim3 grid(DOUTD / 128, CN / 128);
        k_tf32gemm<0><<<grid, 256>>>(a2, W3, t3, CN, DH, DOUTD, nullptr, nullptr, nullptr);
    }
    k_agg_csr<DOUTD, true><<<CN / 2, 128>>>(t3, a3, noff, csrc, cw, dinv,
                                            b3, bns + DH, bnsh + DH);

    // ---- segment mean pool ----
    k_pool_seg<<<CG / 2, 128>>>(a3, goff, pool);

    // ---- MLP head ----
    {
        dim3 grid(DOUTD / 128, CG / 128);
        k_tf32gemm<2><<<grid, 256>>>(pool, Wf1, mlp1, CG, DOUTD, DOUTD, bf1, nullptr, nullptr);
        k_tf32gemm<3><<<grid, 256>>>(mlp1, Wf2, out, CG, DOUTD, DOUTD, bf2, nullptr, nullptr);
    }
}

// round 7
// speedup vs baseline: 4.7475x; 1.5097x over previous
#include <cuda_runtime.h>
#include <cuda_fp16.h>
#include <math.h>
#include <stdint.h>

#define CN 131072
#define CE 524288
#define CG 4096
#define DIN 128
#define DH  512
#define DOUTD 256
#define BN_EPS 1e-5f

// ---------------- scratch (static device globals; no allocation) -------------
__device__ float g_dinv[CN];
__device__ int   g_cnt [CN];
__device__ int   g_noff[CN + 1];
__device__ int   g_cur [CN];
__device__ int   g_bsum[512];
__device__ int   g_csrc[CE];
__device__ float g_cw  [CE];
__device__ int   g_gcnt[CG];
__device__ int   g_goff[CG + 1];
__device__ int   g_gbsum[16];
__device__ float g_bns [DH + DOUTD];
__device__ float g_bnsh[DH + DOUTD];
__device__ __half g_agg1[(size_t)CN * DIN];     // GEMM1 A (fp16)
__device__ __half g_h1  [(size_t)CN * DH];      // GEMM2 A (fp16)
__device__ float  g_t2  [(size_t)CN * DH];      // GEMM2 out (fp32, gathered)
__device__ __half g_a2  [(size_t)CN * DH];      // GEMM3 A (fp16)
__device__ float  g_t3  [(size_t)CN * DOUTD];   // GEMM3 out (fp32, gathered)
__device__ float  g_a3  [(size_t)CN * DOUTD];   // pooled input (fp32)
__device__ __half g_pool[(size_t)CG * DOUTD];   // head GEMM1 A (fp16)
__device__ __half g_mlp1[(size_t)CG * DOUTD];   // head GEMM2 A (fp16)
// fp16 k-pair-packed weights: Wp[k2*N + n] = half2(W[2k2][n], W[2k2+1][n])
__device__ uint32_t g_wp1 [(DIN / 2) * DH];
__device__ uint32_t g_wp2 [(DH / 2) * DH];
__device__ uint32_t g_wp3 [(DH / 2) * DOUTD];
__device__ uint32_t g_wpf1[(DOUTD / 2) * DOUTD];
__device__ uint32_t g_wpf2[(DOUTD / 2) * DOUTD];

// ---------------- small utility kernels --------------------------------------
__global__ void k_zero_i(int* __restrict__ p, int n) {
    unsigned i = blockIdx.x * blockDim.x + threadIdx.x;
    if (i < (unsigned)n) p[i] = 0;
}

__global__ void k_hist(const int* __restrict__ keys, int n, int* __restrict__ cnt) {
    unsigned i = blockIdx.x * blockDim.x + threadIdx.x;
    if (i < (unsigned)n) atomicAdd(&cnt[keys[i]], 1);
}

__global__ void k_dinv_from_cnt(const int* __restrict__ cnt, float* __restrict__ dinv) {
    unsigned i = blockIdx.x * blockDim.x + threadIdx.x;
    if (i < CN) dinv[i] = rsqrtf((float)(cnt[i] + 1));
}

__global__ void k_scan_block(const int* __restrict__ in, int* __restrict__ out,
                             int* __restrict__ bsum, int n) {
    __shared__ int sh[256];
    int t = threadIdx.x;
    int i = blockIdx.x * 256 + t;
    int v = (i < n) ? in[i] : 0;
    sh[t] = v; __syncthreads();
#pragma unroll
    for (int o = 1; o < 256; o <<= 1) {
        int x = (t >= o) ? sh[t - o] : 0;
        __syncthreads();
        sh[t] += x;
        __syncthreads();
    }
    if (i < n) out[i] = sh[t] - v;
    if (t == 255) bsum[blockIdx.x] = sh[255];
}

__global__ void k_scan_partials(int* __restrict__ bsum, int nb) {
    __shared__ int sh[1024];
    int t = threadIdx.x;
    int v = (t < nb) ? bsum[t] : 0;
    sh[t] = v; __syncthreads();
#pragma unroll
    for (int o = 1; o < 1024; o <<= 1) {
        int x = (t >= o) ? sh[t - o] : 0;
        __syncthreads();
        sh[t] += x;
        __syncthreads();
    }
    if (t < nb) bsum[t] = sh[t] - v;
}

__global__ void k_scan_add(int* __restrict__ out, const int* __restrict__ bsum,
                           int n, int total) {
    unsigned i = blockIdx.x * blockDim.x + threadIdx.x;
    if (i < (unsigned)n) out[i] += bsum[i >> 8];
    if (i == 0) out[n] = total;
}

__global__ void k_csr_scatter(const int* __restrict__ src, const int* __restrict__ dst,
                              const float* __restrict__ dinv,
                              const int* __restrict__ noff, int* __restrict__ cur,
                              int* __restrict__ csrc, float* __restrict__ cw) {
    unsigned e = blockIdx.x * blockDim.x + threadIdx.x;
    if (e >= CE) return;
    int d = dst[e], s = src[e];
    int pos = noff[d] + atomicAdd(&cur[d], 1);
    csrc[pos] = s;
    cw[pos] = dinv[s] * dinv[d];
}

__global__ void k_bnprep(const float* __restrict__ g, const float* __restrict__ be,
                         const float* __restrict__ m, const float* __restrict__ v,
                         float* __restrict__ s, float* __restrict__ sh, int n) {
    unsigned i = blockIdx.x * blockDim.x + threadIdx.x;
    if (i >= (unsigned)n) return;
    float sc = g[i] * rsqrtf(v[i] + BN_EPS);
    s[i] = sc;
    sh[i] = be[i] - m[i] * sc;
}

// pack W[K,N] fp32 -> Wp[K/2, N] uint32 (half2 over adjacent k)
__global__ void k_wpack(const float* __restrict__ W, uint32_t* __restrict__ Wp,
                        int K, int N) {
    unsigned i = blockIdx.x * blockDim.x + threadIdx.x;
    if (i >= (unsigned)((K / 2) * N)) return;
    int k2 = i / N, n = i % N;
    __half2 h = __floats2half2_rn(W[(size_t)(2 * k2) * N + n],
                                  W[(size_t)(2 * k2 + 1) * N + n]);
    Wp[i] = *reinterpret_cast<uint32_t*>(&h);
}

// ---------------- CSR aggregation (gather fp32, no atomics) -------------------
// OH: write output as fp16 (half2 pairs); else fp32 float4
template <int D, bool BN, bool OH>
__global__ __launch_bounds__(128) void k_agg_csr(
    const float* __restrict__ t, void* __restrict__ out,
    const int* __restrict__ noff, const int* __restrict__ csrc,
    const float* __restrict__ cw, const float* __restrict__ dinv,
    const float* __restrict__ bias, const float* __restrict__ bns,
    const float* __restrict__ bnsh) {
    constexpr int TPN = D / 4;
    constexpr int NPB = 128 / TPN;
    int node = blockIdx.x * NPB + threadIdx.x / TPN;
    int lane = threadIdx.x % TPN;
    int c = lane * 4;

    float di = dinv[node];
    float4 acc = *reinterpret_cast<const float4*>(t + (size_t)node * D + c);
    float w0 = di * di;
    acc.x *= w0; acc.y *= w0; acc.z *= w0; acc.w *= w0;

    int beg = noff[node], end = noff[node + 1];
    for (int p = beg; p < end; p++) {
        int s = csrc[p];
        float w = cw[p];
        float4 v = *reinterpret_cast<const float4*>(t + (size_t)s * D + c);
        acc.x += v.x * w; acc.y += v.y * w; acc.z += v.z * w; acc.w += v.w * w;
    }
    if (BN) {
        float4 b = *reinterpret_cast<const float4*>(bias + c);
        float4 s4 = *reinterpret_cast<const float4*>(bns + c);
        float4 h4 = *reinterpret_cast<const float4*>(bnsh + c);
        acc.x = fmaxf(acc.x + b.x, 0.0f) * s4.x + h4.x;
        acc.y = fmaxf(acc.y + b.y, 0.0f) * s4.y + h4.y;
        acc.z = fmaxf(acc.z + b.z, 0.0f) * s4.z + h4.z;
        acc.w = fmaxf(acc.w + b.w, 0.0f) * s4.w + h4.w;
    }
    if (OH) {
        __half2* op = reinterpret_cast<__half2*>((__half*)out + (size_t)node * D + c);
        op[0] = __floats2half2_rn(acc.x, acc.y);
        op[1] = __floats2half2_rn(acc.z, acc.w);
    } else {
        *reinterpret_cast<float4*>((float*)out + (size_t)node * D + c) = acc;
    }
}

// ---------------- segment mean pool (fp32 in, fp16 out) -----------------------
__global__ __launch_bounds__(128) void k_pool_seg(const float* __restrict__ h,
                                                  const int* __restrict__ goff,
                                                  __half* __restrict__ pooled) {
    int g = blockIdx.x * 2 + threadIdx.x / 64;
    int lane = threadIdx.x % 64;
    int c = lane * 4;
    int beg = goff[g], end = goff[g + 1];
    float4 acc = make_float4(0.f, 0.f, 0.f, 0.f);
    for (int n = beg; n < end; n++) {
        float4 v = *reinterpret_cast<const float4*>(h + (size_t)n * DOUTD + c);
        acc.x += v.x; acc.y += v.y; acc.z += v.z; acc.w += v.w;
    }
    float inv = 1.0f / fmaxf((float)(end - beg), 1.0f);
    __half2* op = reinterpret_cast<__half2*>(pooled + (size_t)g * DOUTD + c);
    op[0] = __floats2half2_rn(acc.x * inv, acc.y * inv);
    op[1] = __floats2half2_rn(acc.z * inv, acc.w * inv);
}

// ---------------- FP16 tensor-core GEMM (double-buffered) ---------------------
// C[M,Nn] = A[M,K] @ W[K,Nn] (+ epilogue). A fp16 [M,K]; W packed [K/2,N] half2.
// M%128==0, Nn%128==0, K%32==0. Block 128x128, 256 thr = 8 warps (2x4),
// warp tile 64x32, mma m16n8k16. K-chunk 32 (16 half2 rows), 2-stage pipeline.
// Smem element = half2 over k-pair; stride 136 -> conflict-free fragment LDS.
__device__ __forceinline__ void mma_f16(float* c, const uint32_t* a, const uint32_t* b) {
    asm volatile(
        "mma.sync.aligned.m16n8k16.row.col.f32.f16.f16.f32 "
        "{%0,%1,%2,%3}, {%4,%5,%6,%7}, {%8,%9}, {%0,%1,%2,%3};"
        : "+f"(c[0]), "+f"(c[1]), "+f"(c[2]), "+f"(c[3])
        : "r"(a[0]), "r"(a[1]), "r"(a[2]), "r"(a[3]), "r"(b[0]), "r"(b[1]));
}

#define GSTRIDE 136

// EPI: 0=none, 1=bias+relu+BN, 2=bias+relu, 3=bias ; OH: fp16 output
template <int EPI, bool OH>
__global__ __launch_bounds__(256, 2) void k_hgemm(
    const __half* __restrict__ A, const uint32_t* __restrict__ Wp, void* __restrict__ C,
    int M, int K, int Nn,
    const float* __restrict__ bias, const float* __restrict__ bns,
    const float* __restrict__ bnsh) {
    __shared__ uint32_t As[2][16][GSTRIDE];   // [buf][k2][m]
    __shared__ uint32_t Bs[2][16][GSTRIDE];   // [buf][k2][n]

    const int tid = threadIdx.x;
    const int bc = blockIdx.x, br = blockIdx.y;
    const int lane = tid & 31;
    const int wid = tid >> 5;
    const int wm = (wid >> 2) * 64;
    const int wn = (wid & 3) * 32;

    // A staging: row = tid/2 (0..127), k2 base = (tid&1)*8; two uint4 loads
    const int arow = tid >> 1;
    const int ak2 = (tid & 1) * 8;
    // B staging: k2 rows brow, brow+8; cols bn4..bn4+3 (uint32 = half2)
    const int bn4 = (tid & 31) * 4;
    const int brow = tid >> 5;

    const int K2 = K >> 1;
    const uint32_t* Aptr = reinterpret_cast<const uint32_t*>(A)
                           + (size_t)(br * 128 + arow) * K2 + ak2;
    const uint32_t* Bptr = Wp + (size_t)brow * Nn + bc * 128 + bn4;
    const size_t BchunkStep = (size_t)16 * Nn;

    float acc[4][4][4];
#pragma unroll
    for (int mf = 0; mf < 4; mf++)
#pragma unroll
        for (int nf = 0; nf < 4; nf++)
#pragma unroll
            for (int r = 0; r < 4; r++) acc[mf][nf][r] = 0.0f;

    const int nchunks = K >> 5;   // K-chunk = 32 halves = 16 half2

    uint4 ra0, ra1, rb0, rb1;
    // prologue: chunk 0 -> buf 0
    ra0 = *reinterpret_cast<const uint4*>(Aptr);
    ra1 = *reinterpret_cast<const uint4*>(Aptr + 4);
    rb0 = *reinterpret_cast<const uint4*>(Bptr);
    rb1 = *reinterpret_cast<const uint4*>(Bptr + 8 * Nn);
    {
        As[0][ak2 + 0][arow] = ra0.x; As[0][ak2 + 1][arow] = ra0.y;
        As[0][ak2 + 2][arow] = ra0.z; As[0][ak2 + 3][arow] = ra0.w;
        As[0][ak2 + 4][arow] = ra1.x; As[0][ak2 + 5][arow] = ra1.y;
        As[0][ak2 + 6][arow] = ra1.z; As[0][ak2 + 7][arow] = ra1.w;
        *reinterpret_cast<uint4*>(&Bs[0][brow][bn4]) = rb0;
        *reinterpret_cast<uint4*>(&Bs[0][brow + 8][bn4]) = rb1;
    }
    __syncthreads();

    const int gr = lane >> 2;
    const int gc = lane & 3;

    for (int i = 0; i < nchunks; i++) {
        if (i + 1 < nchunks) {
            const uint32_t* Ap = Aptr + (i + 1) * 16;
            const uint32_t* Bp = Bptr + (size_t)(i + 1) * BchunkStep;
            ra0 = *reinterpret_cast<const uint4*>(Ap);
            ra1 = *reinterpret_cast<const uint4*>(Ap + 4);
            rb0 = *reinterpret_cast<const uint4*>(Bp);
            rb1 = *reinterpret_cast<const uint4*>(Bp + 8 * Nn);
        }

        const int cb = i & 1;
#pragma unroll
        for (int ks2 = 0; ks2 < 16; ks2 += 8) {
            uint32_t af[4][4];
#pragma unroll
            for (int mf = 0; mf < 4; mf++) {
                int mb = wm + mf * 16;
                af[mf][0] = As[cb][ks2 + gc][mb + gr];
                af[mf][1] = As[cb][ks2 + gc][mb + gr + 8];
                af[mf][2] = As[cb][ks2 + gc + 4][mb + gr];
                af[mf][3] = As[cb][ks2 + gc + 4][mb + gr + 8];
            }
            uint32_t bf[4][2];
#pragma unroll
            for (int nf = 0; nf < 4; nf++) {
                int nb = wn + nf * 8;
                bf[nf][0] = Bs[cb][ks2 + gc][nb + gr];
                bf[nf][1] = Bs[cb][ks2 + gc + 4][nb + gr];
            }
#pragma unroll
            for (int mf = 0; mf < 4; mf++)
#pragma unroll
                for (int nf = 0; nf < 4; nf++)
                    mma_f16(acc[mf][nf], af[mf], bf[nf]);
        }

        if (i + 1 < nchunks) {
            const int nb2 = (i + 1) & 1;
            As[nb2][ak2 + 0][arow] = ra0.x; As[nb2][ak2 + 1][arow] = ra0.y;
            As[nb2][ak2 + 2][arow] = ra0.z; As[nb2][ak2 + 3][arow] = ra0.w;
            As[nb2][ak2 + 4][arow] = ra1.x; As[nb2][ak2 + 5][arow] = ra1.y;
            As[nb2][ak2 + 6][arow] = ra1.z; As[nb2][ak2 + 7][arow] = ra1.w;
            *reinterpret_cast<uint4*>(&Bs[nb2][brow][bn4]) = rb0;
            *reinterpret_cast<uint4*>(&Bs[nb2][brow + 8][bn4]) = rb1;
        }
        __syncthreads();
    }

    // epilogue + store
    float* Cf = reinterpret_cast<float*>(C);
    __half* Ch = reinterpret_cast<__half*>(C);
#pragma unroll
    for (int nf = 0; nf < 4; nf++) {
        int col = bc * 128 + wn + nf * 8 + gc * 2;
        float bb0 = 0.f, bb1 = 0.f, s0 = 1.f, s1 = 1.f, h0 = 0.f, h1 = 0.f;
        if (EPI != 0) { bb0 = bias[col]; bb1 = bias[col + 1]; }
        if (EPI == 1) {
            s0 = bns[col]; s1 = bns[col + 1];
            h0 = bnsh[col]; h1 = bnsh[col + 1];
        }
#pragma unroll
        for (int mf = 0; mf < 4; mf++) {
            int row0 = br * 128 + wm + mf * 16 + gr;
            float v0 = acc[mf][nf][0], v1 = acc[mf][nf][1];
            float v2 = acc[mf][nf][2], v3 = acc[mf][nf][3];
            if (EPI != 0) { v0 += bb0; v1 += bb1; v2 += bb0; v3 += bb1; }
            if (EPI == 1 || EPI == 2) {
                v0 = fmaxf(v0, 0.f); v1 = fmaxf(v1, 0.f);
                v2 = fmaxf(v2, 0.f); v3 = fmaxf(v3, 0.f);
            }
            if (EPI == 1) {
                v0 = v0 * s0 + h0; v1 = v1 * s1 + h1;
                v2 = v2 * s0 + h0; v3 = v3 * s1 + h1;
            }
            if (OH) {
                *reinterpret_cast<__half2*>(Ch + (size_t)row0 * Nn + col) =
                    __floats2half2_rn(v0, v1);
                *reinterpret_cast<__half2*>(Ch + (size_t)(row0 + 8) * Nn + col) =
                    __floats2half2_rn(v2, v3);
            } else {
                *reinterpret_cast<float2*>(Cf + (size_t)row0 * Nn + col) = make_float2(v0, v1);
                *reinterpret_cast<float2*>(Cf + (size_t)(row0 + 8) * Nn + col) = make_float2(v2, v3);
            }
        }
    }
}

// ---------------- launch -----------------------------------------------------
extern "C" void kernel_launch(void* const* d_in, const int* in_sizes, int n_in,
                              void* d_out, int out_size) {
    const float* x   = (const float*)d_in[0];
    const int* ei    = (const int*)d_in[1];
    const int* batch = (const int*)d_in[2];
    const float* W1  = (const float*)d_in[3];  const float* b1  = (const float*)d_in[4];
    const float* W2  = (const float*)d_in[5];  const float* b2  = (const float*)d_in[6];
    const float* W3  = (const float*)d_in[7];  const float* b3  = (const float*)d_in[8];
    const float* g1  = (const float*)d_in[9];  const float* be1 = (const float*)d_in[10];
    const float* m1  = (const float*)d_in[11]; const float* v1  = (const float*)d_in[12];
    const float* g2  = (const float*)d_in[13]; const float* be2 = (const float*)d_in[14];
    const float* m2  = (const float*)d_in[15]; const float* v2  = (const float*)d_in[16];
    const float* g3  = (const float*)d_in[17]; const float* be3 = (const float*)d_in[18];
    const float* m3  = (const float*)d_in[19]; const float* v3  = (const float*)d_in[20];
    const float* Wf1 = (const float*)d_in[21]; const float* bf1 = (const float*)d_in[22];
    const float* Wf2 = (const float*)d_in[23]; const float* bf2 = (const float*)d_in[24];
    float* out = (float*)d_out;

    const int* src = ei;
    const int* dst = ei + CE;

    float *dinv, *cw, *t2, *t3, *a3, *bns, *bnsh;
    __half *agg1, *h1, *a2, *pool, *mlp1;
    uint32_t *wp1, *wp2, *wp3, *wpf1, *wpf2;
    int *cnt, *noff, *cur, *bsum, *csrc, *gcnt, *goff, *gbsum;
    cudaGetSymbolAddress((void**)&dinv, g_dinv);
    cudaGetSymbolAddress((void**)&cnt,  g_cnt);
    cudaGetSymbolAddress((void**)&noff, g_noff);
    cudaGetSymbolAddress((void**)&cur,  g_cur);
    cudaGetSymbolAddress((void**)&bsum, g_bsum);
    cudaGetSymbolAddress((void**)&csrc, g_csrc);
    cudaGetSymbolAddress((void**)&cw,   g_cw);
    cudaGetSymbolAddress((void**)&gcnt, g_gcnt);
    cudaGetSymbolAddress((void**)&goff, g_goff);
    cudaGetSymbolAddress((void**)&gbsum, g_gbsum);
    cudaGetSymbolAddress((void**)&bns,  g_bns);
    cudaGetSymbolAddress((void**)&bnsh, g_bnsh);
    cudaGetSymbolAddress((void**)&agg1, g_agg1);
    cudaGetSymbolAddress((void**)&h1,   g_h1);
    cudaGetSymbolAddress((void**)&t2,   g_t2);
    cudaGetSymbolAddress((void**)&a2,   g_a2);
    cudaGetSymbolAddress((void**)&t3,   g_t3);
    cudaGetSymbolAddress((void**)&a3,   g_a3);
    cudaGetSymbolAddress((void**)&pool, g_pool);
    cudaGetSymbolAddress((void**)&mlp1, g_mlp1);
    cudaGetSymbolAddress((void**)&wp1,  g_wp1);
    cudaGetSymbolAddress((void**)&wp2,  g_wp2);
    cudaGetSymbolAddress((void**)&wp3,  g_wp3);
    cudaGetSymbolAddress((void**)&wpf1, g_wpf1);
    cudaGetSymbolAddress((void**)&wpf2, g_wpf2);

    const int T = 256;

    // ---- pack weights to fp16 (k-pair half2) ----
    k_wpack<<<((DIN / 2) * DH + T - 1) / T, T>>>(W1, wp1, DIN, DH);
    k_wpack<<<((DH / 2) * DH + T - 1) / T, T>>>(W2, wp2, DH, DH);
    k_wpack<<<((DH / 2) * DOUTD + T - 1) / T, T>>>(W3, wp3, DH, DOUTD);
    k_wpack<<<((DOUTD / 2) * DOUTD + T - 1) / T, T>>>(Wf1, wpf1, DOUTD, DOUTD);
    k_wpack<<<((DOUTD / 2) * DOUTD + T - 1) / T, T>>>(Wf2, wpf2, DOUTD, DOUTD);

    // ---- CSR build ----
    k_zero_i<<<(CN + T - 1) / T, T>>>(cnt, CN);
    k_zero_i<<<(CN + T - 1) / T, T>>>(cur, CN);
    k_zero_i<<<(CG + T - 1) / T, T>>>(gcnt, CG);
    k_hist<<<(CE + T - 1) / T, T>>>(dst, CE, cnt);
    k_hist<<<(CN + T - 1) / T, T>>>(batch, CN, gcnt);
    k_dinv_from_cnt<<<(CN + T - 1) / T, T>>>(cnt, dinv);
    k_scan_block<<<CN / 256, 256>>>(cnt, noff, bsum, CN);
    k_scan_partials<<<1, 1024>>>(bsum, CN / 256);
    k_scan_add<<<(CN + T - 1) / T, T>>>(noff, bsum, CN, CE);
    k_scan_block<<<CG / 256, 256>>>(gcnt, goff, gbsum, CG);
    k_scan_partials<<<1, 1024>>>(gbsum, CG / 256);
    k_scan_add<<<(CG + T - 1) / T, T>>>(goff, gbsum, CG, CN);
    k_csr_scatter<<<(CE + T - 1) / T, T>>>(src, dst, dinv, noff, cur, csrc, cw);

    // ---- layer1 BN consts ----
    k_bnprep<<<(DH + T - 1) / T, T>>>(g1, be1, m1, v1, bns, bnsh, DH);

    // ---- layer 1: aggregate (D=128, fp16 out) then GEMM (bias+relu+BN, fp16 out) ----
    k_agg_csr<DIN, false, true><<<CN / 4, 128>>>(x, agg1, noff, csrc, cw, dinv,
                                                 nullptr, nullptr, nullptr);
    {
        dim3 grid(DH / 128, CN / 128);
        k_hgemm<1, true><<<grid, 256>>>(agg1, wp1, h1, CN, DIN, DH, b1, bns, bnsh);
    }

    // re-prep BN consts for layers 2 & 3
    k_bnprep<<<(DH + T - 1) / T, T>>>(g2, be2, m2, v2, bns, bnsh, DH);
    k_bnprep<<<(DOUTD + T - 1) / T, T>>>(g3, be3, m3, v3, bns + DH, bnsh + DH, DOUTD);

    // ---- layer 2: GEMM (fp32 out) then aggregate (fp16 out) ----
    {
        dim3 grid(DH / 128, CN / 128);
        k_hgemm<0, false><<<grid, 256>>>(h1, wp2, t2, CN, DH, DH, nullptr, nullptr, nullptr);
    }
    k_agg_csr<DH, true, true><<<CN, 128>>>(t2, a2, noff, csrc, cw, dinv, b2, bns, bnsh);

    // ---- layer 3: GEMM (fp32 out) then aggregate (fp32 out) ----
    {
        dim3 grid(DOUTD / 128, CN / 128);
        k_hgemm<0, false><<<grid, 256>>>(a2, wp3, t3, CN, DH, DOUTD, nullptr, nullptr, nullptr);
    }
    k_agg_csr<DOUTD, true, false><<<CN / 2, 128>>>(t3, a3, noff, csrc, cw, dinv,
                                                   b3, bns + DH, bnsh + DH);

    // ---- segment mean pool (fp16 out) ----
    k_pool_seg<<<CG / 2, 128>>>(a3, goff, pool);

    // ---- MLP head ----
    {
        dim3 grid(DOUTD / 128, CG / 128);
        k_hgemm<2, true><<<grid, 256>>>(pool, wpf1, mlp1, CG, DOUTD, DOUTD, bf1, nullptr, nullptr);
        k_hgemm<3, false><<<grid, 256>>>(mlp1, wpf2, out, CG, DOUTD, DOUTD, bf2, nullptr, nullptr);
    }
}